// round 1
// baseline (speedup 1.0000x reference)
#include <cuda_runtime.h>
#include <math.h>

#define DIM    1024
#define HEADS  16
#define DH     64
#define SEG    512
#define PMEM   16
#define BATCH  2
#define NSEQ   4096
#define WSEG   (NSEQ / SEG)       // 8
#define BW     (BATCH * WSEG)     // 16
#define ROWS   (BATCH * NSEQ)     // 8192
#define KV     (SEG + PMEM)       // 528
#define RMS_EPS 1.1920929e-07f

// ---------------- scratch (no cudaMalloc allowed) ----------------
__device__ float g_xn [(size_t)ROWS * DIM];          // 32 MB  RMSNorm output
__device__ float g_qkv[(size_t)ROWS * 3 * DIM];      // 96 MB  QKV projection
__device__ float g_q  [(size_t)BW * HEADS * SEG * DH];
__device__ float g_k  [(size_t)BW * HEADS * KV  * DH];
__device__ float g_v  [(size_t)BW * HEADS * KV  * DH];
__device__ float g_ao [(size_t)ROWS * DIM];          // 32 MB  attention out (pre-proj)

// ---------------- RMSNorm ----------------
__global__ __launch_bounds__(256) void rmsnorm_kernel(const float* __restrict__ seq,
                                                      const float* __restrict__ g,
                                                      float* __restrict__ xn) {
    int row = blockIdx.x;
    int tid = threadIdx.x;
    const float4* in = (const float4*)(seq + (size_t)row * DIM);
    float4 v = in[tid];
    float ss = v.x * v.x + v.y * v.y + v.z * v.z + v.w * v.w;
    #pragma unroll
    for (int o = 16; o; o >>= 1) ss += __shfl_xor_sync(0xFFFFFFFFu, ss, o);
    __shared__ float wsum[8];
    __shared__ float srms;
    if ((tid & 31) == 0) wsum[tid >> 5] = ss;
    __syncthreads();
    if (tid == 0) {
        float t = 0.f;
        #pragma unroll
        for (int i = 0; i < 8; i++) t += wsum[i];
        srms = rsqrtf(t * (1.0f / DIM) + RMS_EPS);
    }
    __syncthreads();
    float r = srms;
    float4 gv = ((const float4*)g)[tid];
    float4 o;
    o.x = v.x * r * gv.x; o.y = v.y * r * gv.y;
    o.z = v.z * r * gv.z; o.w = v.w * r * gv.w;
    ((float4*)(xn + (size_t)row * DIM))[tid] = o;
}

// ---------------- SGEMM: C[M,N] = A[M,K] * B[N,K]^T (both K-contiguous) ----------------
#define BM 128
#define BN 128
#define BKT 16
__global__ __launch_bounds__(256) void sgemm_nt(const float* __restrict__ A,
                                                const float* __restrict__ Bm,
                                                float* __restrict__ C,
                                                int M, int Nn, int K) {
    __shared__ float As[BKT][BM + 4];
    __shared__ float Bs[BKT][BN + 4];
    int tid = threadIdx.x;
    int bm = blockIdx.y * BM;
    int bn = blockIdx.x * BN;
    int tx = tid & 15;        // 0..15 -> 8 cols each
    int ty = tid >> 4;        // 0..15 -> 8 rows each
    int lr = tid >> 2;        // 0..63
    int lk = (tid & 3) * 4;   // 0,4,8,12

    const float* Aptr = A  + (size_t)bm * K;
    const float* Bptr = Bm + (size_t)bn * K;

    float acc[8][8];
    #pragma unroll
    for (int i = 0; i < 8; i++)
        #pragma unroll
        for (int j = 0; j < 8; j++) acc[i][j] = 0.f;

    for (int k0 = 0; k0 < K; k0 += BKT) {
        float4 a0 = *(const float4*)(Aptr + (size_t)lr * K        + k0 + lk);
        float4 a1 = *(const float4*)(Aptr + (size_t)(lr + 64) * K + k0 + lk);
        float4 b0 = *(const float4*)(Bptr + (size_t)lr * K        + k0 + lk);
        float4 b1 = *(const float4*)(Bptr + (size_t)(lr + 64) * K + k0 + lk);
        As[lk + 0][lr] = a0.x; As[lk + 1][lr] = a0.y; As[lk + 2][lr] = a0.z; As[lk + 3][lr] = a0.w;
        As[lk + 0][lr + 64] = a1.x; As[lk + 1][lr + 64] = a1.y; As[lk + 2][lr + 64] = a1.z; As[lk + 3][lr + 64] = a1.w;
        Bs[lk + 0][lr] = b0.x; Bs[lk + 1][lr] = b0.y; Bs[lk + 2][lr] = b0.z; Bs[lk + 3][lr] = b0.w;
        Bs[lk + 0][lr + 64] = b1.x; Bs[lk + 1][lr + 64] = b1.y; Bs[lk + 2][lr + 64] = b1.z; Bs[lk + 3][lr + 64] = b1.w;
        __syncthreads();
        #pragma unroll
        for (int kk = 0; kk < BKT; kk++) {
            float4 fa0 = *(const float4*)&As[kk][ty * 8];
            float4 fa1 = *(const float4*)&As[kk][ty * 8 + 4];
            float4 fb0 = *(const float4*)&Bs[kk][tx * 8];
            float4 fb1 = *(const float4*)&Bs[kk][tx * 8 + 4];
            float ar[8] = {fa0.x, fa0.y, fa0.z, fa0.w, fa1.x, fa1.y, fa1.z, fa1.w};
            float br[8] = {fb0.x, fb0.y, fb0.z, fb0.w, fb1.x, fb1.y, fb1.z, fb1.w};
            #pragma unroll
            for (int i = 0; i < 8; i++)
                #pragma unroll
                for (int j = 0; j < 8; j++)
                    acc[i][j] = fmaf(ar[i], br[j], acc[i][j]);
        }
        __syncthreads();
    }
    #pragma unroll
    for (int i = 0; i < 8; i++) {
        float* cp = C + (size_t)(bm + ty * 8 + i) * Nn + bn + tx * 8;
        *(float4*)cp       = make_float4(acc[i][0], acc[i][1], acc[i][2], acc[i][3]);
        *(float4*)(cp + 4) = make_float4(acc[i][4], acc[i][5], acc[i][6], acc[i][7]);
    }
}

// ---------------- persistent-memory prepend ----------------
__global__ __launch_bounds__(1024) void pm_fill(const float* __restrict__ pm,
                                                float* __restrict__ k,
                                                float* __restrict__ v) {
    int bwh = blockIdx.x;          // 0..255: bw*16+h
    int h = bwh & 15;
    int t = threadIdx.x;           // 0..1023
    int p = t >> 6;                // 0..15
    int d = t & 63;
    float kv_ = pm[((size_t)h * PMEM + p) * DH + d];
    float vv_ = pm[(size_t)HEADS * PMEM * DH + ((size_t)h * PMEM + p) * DH + d];
    k[((size_t)bwh * KV + p) * DH + d] = kv_;
    v[((size_t)bwh * KV + p) * DH + d] = vv_;
}

// ---------------- RoPE + reshape + segment scatter ----------------
__global__ __launch_bounds__(512) void rope_scatter(const float* __restrict__ qkv,
                                                    float* __restrict__ q,
                                                    float* __restrict__ k,
                                                    float* __restrict__ v) {
    int m = blockIdx.x;            // 0..8191: b*4096 + npos
    int b = m >> 12;
    int npos = m & 4095;
    int t = threadIdx.x;
    int h = t >> 5;                // 0..15
    int d = (t & 31) * 2;          // even dim

    const float* row = qkv + (size_t)m * 3 * DIM;
    float2 qv = *(const float2*)(row + h * DH + d);
    float2 kv2 = *(const float2*)(row + DIM + h * DH + d);
    float2 vv = *(const float2*)(row + 2 * DIM + h * DH + d);

    // mimic reference: inv_freq = 1 / 10000**(d/64) in fp32
    float inv = 1.0f / powf(10000.0f, (float)d * (1.0f / 64.0f));
    float ang = (float)npos * inv;
    float sn, cs;
    sincosf(ang, &sn, &cs);
    float2 qr, kr;
    qr.x = qv.x * cs - qv.y * sn;  qr.y = qv.y * cs + qv.x * sn;
    kr.x = kv2.x * cs - kv2.y * sn; kr.y = kv2.y * cs + kv2.x * sn;

    int w = npos >> 9;
    int sidx = npos & 511;
    int bwh = (b * WSEG + w) * HEADS + h;
    *(float2*)(q + ((size_t)bwh * SEG + sidx) * DH + d) = qr;
    *(float2*)(k + ((size_t)bwh * KV + PMEM + sidx) * DH + d) = kr;
    *(float2*)(v + ((size_t)bwh * KV + PMEM + sidx) * DH + d) = vv;
}

// ---------------- flash attention (fp32, 1 query/thread) ----------------
__global__ __launch_bounds__(256, 1) void attn_kernel(const float* __restrict__ Q,
                                                      const float* __restrict__ K,
                                                      const float* __restrict__ V,
                                                      float* __restrict__ AO) {
    __shared__ float4 sK[64 * 16];
    __shared__ float4 sV[64 * 16];

    int bwh = blockIdx.x >> 1;     // 0..255
    int half = blockIdx.x & 1;
    int qbase = half << 8;
    int tid = threadIdx.x;
    int qi = qbase + tid;          // within-segment query index
    int bw = bwh >> 4;
    int h  = bwh & 15;

    const float* Kb = K + (size_t)bwh * KV * DH;
    const float* Vb = V + (size_t)bwh * KV * DH;

    float4 q4[16];
    {
        const float4* qp = (const float4*)(Q + ((size_t)bwh * SEG + qi) * DH);
        #pragma unroll
        for (int dd = 0; dd < 16; dd++) q4[dd] = qp[dd];
    }
    float4 o4[16];
    #pragma unroll
    for (int dd = 0; dd < 16; dd++) o4[dd] = make_float4(0.f, 0.f, 0.f, 0.f);
    float mrun = -1e30f;
    float lrun = 0.f;

    int jcount = qbase + 256 + PMEM;        // max visible key count for this block
    if (jcount > KV) jcount = KV;
    int ntiles = (jcount + 63) >> 6;

    int lrow = tid >> 2;            // 0..63
    int lc0  = (tid & 3) * 4;       // float4 index 0,4,8,12

    for (int kt = 0; kt < ntiles; kt++) {
        int jj0 = kt * 64;
        // stage K/V tile
        {
            int jj = jj0 + lrow;
            if (jj < KV) {
                const float4* kg = (const float4*)(Kb + (size_t)jj * DH);
                const float4* vg = (const float4*)(Vb + (size_t)jj * DH);
                #pragma unroll
                for (int u = 0; u < 4; u++) {
                    sK[lrow * 16 + lc0 + u] = kg[lc0 + u];
                    sV[lrow * 16 + lc0 + u] = vg[lc0 + u];
                }
            }
        }
        __syncthreads();
        int jlimit = jcount - jj0;
        if (jlimit > 64) jlimit = 64;
        for (int j = 0; j < jlimit; j++) {
            int jj = jj0 + j;
            bool vis = (jj <= qi + PMEM);
            if (vis) {
                float s0 = 0.f, s1 = 0.f, s2 = 0.f, s3 = 0.f;
                #pragma unroll
                for (int dd = 0; dd < 16; dd++) {
                    float4 kk = sK[j * 16 + dd];
                    float4 qq = q4[dd];
                    s0 = fmaf(qq.x, kk.x, s0);
                    s1 = fmaf(qq.y, kk.y, s1);
                    s2 = fmaf(qq.z, kk.z, s2);
                    s3 = fmaf(qq.w, kk.w, s3);
                }
                float sc = (s0 + s1) + (s2 + s3);
                sc *= 0.125f;
                if (sc > mrun) {
                    float c = expf(mrun - sc);
                    lrun *= c;
                    #pragma unroll
                    for (int dd = 0; dd < 16; dd++) {
                        o4[dd].x *= c; o4[dd].y *= c; o4[dd].z *= c; o4[dd].w *= c;
                    }
                    mrun = sc;
                }
                float p = expf(sc - mrun);
                lrun += p;
                #pragma unroll
                for (int dd = 0; dd < 16; dd++) {
                    float4 vv = sV[j * 16 + dd];
                    o4[dd].x = fmaf(p, vv.x, o4[dd].x);
                    o4[dd].y = fmaf(p, vv.y, o4[dd].y);
                    o4[dd].z = fmaf(p, vv.z, o4[dd].z);
                    o4[dd].w = fmaf(p, vv.w, o4[dd].w);
                }
            }
        }
        __syncthreads();
    }

    float invl = 1.0f / lrun;
    float4* op = (float4*)(AO + (size_t)(bw * SEG + qi) * DIM + h * DH);
    #pragma unroll
    for (int dd = 0; dd < 16; dd++) {
        float4 o = o4[dd];
        o.x *= invl; o.y *= invl; o.z *= invl; o.w *= invl;
        op[dd] = o;
    }
}

// ---------------- launch ----------------
extern "C" void kernel_launch(void* const* d_in, const int* in_sizes, int n_in,
                              void* d_out, int out_size) {
    const float* seq   = (const float*)d_in[0];
    const float* g     = (const float*)d_in[1];
    const float* w_qkv = (const float*)d_in[2];
    const float* w_out = (const float*)d_in[3];
    const float* pm    = (const float*)d_in[4];
    float* out = (float*)d_out;

    float *xn, *qkv, *q, *k, *v, *ao;
    cudaGetSymbolAddress((void**)&xn,  g_xn);
    cudaGetSymbolAddress((void**)&qkv, g_qkv);
    cudaGetSymbolAddress((void**)&q,   g_q);
    cudaGetSymbolAddress((void**)&k,   g_k);
    cudaGetSymbolAddress((void**)&v,   g_v);
    cudaGetSymbolAddress((void**)&ao,  g_ao);

    rmsnorm_kernel<<<ROWS, 256>>>(seq, g, xn);
    sgemm_nt<<<dim3(3 * DIM / BN, ROWS / BM), 256>>>(xn, w_qkv, qkv, ROWS, 3 * DIM, DIM);
    pm_fill<<<BW * HEADS, 1024>>>(pm, k, v);
    rope_scatter<<<ROWS, 512>>>(qkv, q, k, v);
    attn_kernel<<<BW * HEADS * 2, 256>>>(q, k, v, ao);
    sgemm_nt<<<dim3(DIM / BN, ROWS / BM), 256>>>(ao, w_out, out, ROWS, DIM, DIM);
}

// round 2
// speedup vs baseline: 2.0487x; 2.0487x over previous
#include <cuda_runtime.h>
#include <math.h>

#define DIM    1024
#define HEADS  16
#define DH     64
#define SEG    512
#define PMEM   16
#define BATCH  2
#define NSEQ   4096
#define WSEG   (NSEQ / SEG)       // 8
#define BW     (BATCH * WSEG)     // 16
#define ROWS   (BATCH * NSEQ)     // 8192
#define KV     (SEG + PMEM)       // 528
#define RMS_EPS 1.1920929e-07f

// ---------------- scratch (no cudaMalloc allowed) ----------------
__device__ float g_xn [(size_t)ROWS * DIM];          // 32 MB  RMSNorm output
__device__ float g_qkv[(size_t)ROWS * 3 * DIM];      // 96 MB  QKV projection
__device__ float g_q  [(size_t)BW * HEADS * SEG * DH];
__device__ float g_k  [(size_t)BW * HEADS * KV  * DH];
__device__ float g_v  [(size_t)BW * HEADS * KV  * DH];
__device__ float g_ao [(size_t)ROWS * DIM];          // 32 MB  attention out (pre-proj)

// ---------------- RMSNorm ----------------
__global__ __launch_bounds__(256) void rmsnorm_kernel(const float* __restrict__ seq,
                                                      const float* __restrict__ g,
                                                      float* __restrict__ xn) {
    int row = blockIdx.x;
    int tid = threadIdx.x;
    const float4* in = (const float4*)(seq + (size_t)row * DIM);
    float4 v = in[tid];
    float ss = v.x * v.x + v.y * v.y + v.z * v.z + v.w * v.w;
    #pragma unroll
    for (int o = 16; o; o >>= 1) ss += __shfl_xor_sync(0xFFFFFFFFu, ss, o);
    __shared__ float wsum[8];
    __shared__ float srms;
    if ((tid & 31) == 0) wsum[tid >> 5] = ss;
    __syncthreads();
    if (tid == 0) {
        float t = 0.f;
        #pragma unroll
        for (int i = 0; i < 8; i++) t += wsum[i];
        srms = rsqrtf(t * (1.0f / DIM) + RMS_EPS);
    }
    __syncthreads();
    float r = srms;
    float4 gv = ((const float4*)g)[tid];
    float4 o;
    o.x = v.x * r * gv.x; o.y = v.y * r * gv.y;
    o.z = v.z * r * gv.z; o.w = v.w * r * gv.w;
    ((float4*)(xn + (size_t)row * DIM))[tid] = o;
}

// ---------------- TF32 tensor-core GEMM: C[M,N] = A[M,K] * B[N,K]^T ----------------
// CTA tile 128x128, 8 warps (4m x 2n), warp tile 32x64, mma.m16n8k8.tf32
#define BM 128
#define BN 128
#define KC 32
#define SPAD 36   // smem row stride in floats (pad for bank-conflict-free frag loads)

__device__ __forceinline__ unsigned f2tf32(float f) {
    unsigned r;
    asm("cvt.rna.tf32.f32 %0, %1;" : "=r"(r) : "f"(f));
    return r;
}

__global__ __launch_bounds__(256) void sgemm_tf32(const float* __restrict__ A,
                                                  const float* __restrict__ Bm,
                                                  float* __restrict__ C,
                                                  int M, int Nn, int K) {
    __shared__ float As[BM][SPAD];
    __shared__ float Bs[BN][SPAD];

    int tid = threadIdx.x;
    int bm = blockIdx.y * BM;
    int bn = blockIdx.x * BN;

    int wid  = tid >> 5;
    int lane = tid & 31;
    int warp_m = (wid & 3) * 32;
    int warp_n = (wid >> 2) * 64;
    int grp = lane >> 2;      // 0..7
    int qid = lane & 3;       // 0..3

    // load mapping: 4 float4 per thread per matrix
    int lrow = tid >> 3;      // 0..31 (+32*i)
    int lc4  = tid & 7;       // 0..7 float4 cols

    const float* Ag = A  + (size_t)(bm + lrow) * K + lc4 * 4;
    const float* Bg = Bm + (size_t)(bn + lrow) * K + lc4 * 4;

    float c[2][8][4];
    #pragma unroll
    for (int i = 0; i < 2; i++)
        #pragma unroll
        for (int j = 0; j < 8; j++)
            #pragma unroll
            for (int u = 0; u < 4; u++) c[i][j][u] = 0.f;

    float4 ra[4], rb[4];

    // prologue: load tile k0=0
    #pragma unroll
    for (int i = 0; i < 4; i++) {
        ra[i] = *(const float4*)(Ag + (size_t)(32 * i) * K);
        rb[i] = *(const float4*)(Bg + (size_t)(32 * i) * K);
    }

    for (int k0 = 0; k0 < K; k0 += KC) {
        // store staged regs (converted to tf32 bit patterns) into smem
        #pragma unroll
        for (int i = 0; i < 4; i++) {
            float4 a = ra[i], b = rb[i];
            a.x = __uint_as_float(f2tf32(a.x)); a.y = __uint_as_float(f2tf32(a.y));
            a.z = __uint_as_float(f2tf32(a.z)); a.w = __uint_as_float(f2tf32(a.w));
            b.x = __uint_as_float(f2tf32(b.x)); b.y = __uint_as_float(f2tf32(b.y));
            b.z = __uint_as_float(f2tf32(b.z)); b.w = __uint_as_float(f2tf32(b.w));
            *(float4*)&As[lrow + 32 * i][lc4 * 4] = a;
            *(float4*)&Bs[lrow + 32 * i][lc4 * 4] = b;
        }
        __syncthreads();

        // issue next tile's global loads early (latency overlap)
        if (k0 + KC < K) {
            #pragma unroll
            for (int i = 0; i < 4; i++) {
                ra[i] = *(const float4*)(Ag + (size_t)(32 * i) * K + k0 + KC);
                rb[i] = *(const float4*)(Bg + (size_t)(32 * i) * K + k0 + KC);
            }
        }

        // compute 4 k8 steps
        #pragma unroll
        for (int ks = 0; ks < KC; ks += 8) {
            unsigned af[2][4];
            #pragma unroll
            for (int mf = 0; mf < 2; mf++) {
                int row = warp_m + mf * 16 + grp;
                af[mf][0] = __float_as_uint(As[row    ][ks + qid    ]);
                af[mf][1] = __float_as_uint(As[row + 8][ks + qid    ]);
                af[mf][2] = __float_as_uint(As[row    ][ks + qid + 4]);
                af[mf][3] = __float_as_uint(As[row + 8][ks + qid + 4]);
            }
            unsigned bf[8][2];
            #pragma unroll
            for (int nf = 0; nf < 8; nf++) {
                int n = warp_n + nf * 8 + grp;
                bf[nf][0] = __float_as_uint(Bs[n][ks + qid    ]);
                bf[nf][1] = __float_as_uint(Bs[n][ks + qid + 4]);
            }
            #pragma unroll
            for (int mf = 0; mf < 2; mf++)
                #pragma unroll
                for (int nf = 0; nf < 8; nf++) {
                    asm volatile(
                        "mma.sync.aligned.m16n8k8.row.col.f32.tf32.tf32.f32 "
                        "{%0,%1,%2,%3}, {%4,%5,%6,%7}, {%8,%9}, {%0,%1,%2,%3};"
                        : "+f"(c[mf][nf][0]), "+f"(c[mf][nf][1]),
                          "+f"(c[mf][nf][2]), "+f"(c[mf][nf][3])
                        : "r"(af[mf][0]), "r"(af[mf][1]), "r"(af[mf][2]), "r"(af[mf][3]),
                          "r"(bf[nf][0]), "r"(bf[nf][1]));
                }
        }
        __syncthreads();
    }

    // epilogue
    #pragma unroll
    for (int mf = 0; mf < 2; mf++) {
        int row0 = bm + warp_m + mf * 16 + grp;
        #pragma unroll
        for (int nf = 0; nf < 8; nf++) {
            int col = bn + warp_n + nf * 8 + qid * 2;
            *(float2*)(C + (size_t)row0 * Nn + col)       = make_float2(c[mf][nf][0], c[mf][nf][1]);
            *(float2*)(C + (size_t)(row0 + 8) * Nn + col) = make_float2(c[mf][nf][2], c[mf][nf][3]);
        }
    }
}

// ---------------- persistent-memory prepend ----------------
__global__ __launch_bounds__(1024) void pm_fill(const float* __restrict__ pm,
                                                float* __restrict__ k,
                                                float* __restrict__ v) {
    int bwh = blockIdx.x;          // 0..255: bw*16+h
    int h = bwh & 15;
    int t = threadIdx.x;           // 0..1023
    int p = t >> 6;                // 0..15
    int d = t & 63;
    float kv_ = pm[((size_t)h * PMEM + p) * DH + d];
    float vv_ = pm[(size_t)HEADS * PMEM * DH + ((size_t)h * PMEM + p) * DH + d];
    k[((size_t)bwh * KV + p) * DH + d] = kv_;
    v[((size_t)bwh * KV + p) * DH + d] = vv_;
}

// ---------------- RoPE + reshape + segment scatter ----------------
__global__ __launch_bounds__(512) void rope_scatter(const float* __restrict__ qkv,
                                                    float* __restrict__ q,
                                                    float* __restrict__ k,
                                                    float* __restrict__ v) {
    int m = blockIdx.x;            // 0..8191: b*4096 + npos
    int b = m >> 12;
    int npos = m & 4095;
    int t = threadIdx.x;
    int h = t >> 5;                // 0..15
    int d = (t & 31) * 2;          // even dim

    const float* row = qkv + (size_t)m * 3 * DIM;
    float2 qv = *(const float2*)(row + h * DH + d);
    float2 kv2 = *(const float2*)(row + DIM + h * DH + d);
    float2 vv = *(const float2*)(row + 2 * DIM + h * DH + d);

    // mimic reference: inv_freq = 1 / 10000**(d/64) in fp32
    float inv = 1.0f / powf(10000.0f, (float)d * (1.0f / 64.0f));
    float ang = (float)npos * inv;
    float sn, cs;
    sincosf(ang, &sn, &cs);
    float2 qr, kr;
    qr.x = qv.x * cs - qv.y * sn;  qr.y = qv.y * cs + qv.x * sn;
    kr.x = kv2.x * cs - kv2.y * sn; kr.y = kv2.y * cs + kv2.x * sn;

    int w = npos >> 9;
    int sidx = npos & 511;
    int bwh = (b * WSEG + w) * HEADS + h;
    *(float2*)(q + ((size_t)bwh * SEG + sidx) * DH + d) = qr;
    *(float2*)(k + ((size_t)bwh * KV + PMEM + sidx) * DH + d) = kr;
    *(float2*)(v + ((size_t)bwh * KV + PMEM + sidx) * DH + d) = vv;
}

// ---------------- flash attention (fp32, 1 query/thread) ----------------
__global__ __launch_bounds__(256, 1) void attn_kernel(const float* __restrict__ Q,
                                                      const float* __restrict__ K,
                                                      const float* __restrict__ V,
                                                      float* __restrict__ AO) {
    __shared__ float4 sK[64 * 16];
    __shared__ float4 sV[64 * 16];

    int bwh = blockIdx.x >> 1;     // 0..255
    int half = blockIdx.x & 1;
    int qbase = half << 8;
    int tid = threadIdx.x;
    int qi = qbase + tid;          // within-segment query index
    int bw = bwh >> 4;
    int h  = bwh & 15;

    const float* Kb = K + (size_t)bwh * KV * DH;
    const float* Vb = V + (size_t)bwh * KV * DH;

    float4 q4[16];
    {
        const float4* qp = (const float4*)(Q + ((size_t)bwh * SEG + qi) * DH);
        #pragma unroll
        for (int dd = 0; dd < 16; dd++) q4[dd] = qp[dd];
    }
    float4 o4[16];
    #pragma unroll
    for (int dd = 0; dd < 16; dd++) o4[dd] = make_float4(0.f, 0.f, 0.f, 0.f);
    float mrun = -1e30f;
    float lrun = 0.f;

    int jcount = qbase + 256 + PMEM;        // max visible key count for this block
    if (jcount > KV) jcount = KV;
    int ntiles = (jcount + 63) >> 6;

    int lrow = tid >> 2;            // 0..63
    int lc0  = (tid & 3) * 4;       // float4 index 0,4,8,12

    for (int kt = 0; kt < ntiles; kt++) {
        int jj0 = kt * 64;
        // stage K/V tile
        {
            int jj = jj0 + lrow;
            if (jj < KV) {
                const float4* kg = (const float4*)(Kb + (size_t)jj * DH);
                const float4* vg = (const float4*)(Vb + (size_t)jj * DH);
                #pragma unroll
                for (int u = 0; u < 4; u++) {
                    sK[lrow * 16 + lc0 + u] = kg[lc0 + u];
                    sV[lrow * 16 + lc0 + u] = vg[lc0 + u];
                }
            }
        }
        __syncthreads();
        int jlimit = jcount - jj0;
        if (jlimit > 64) jlimit = 64;
        for (int j = 0; j < jlimit; j++) {
            int jj = jj0 + j;
            bool vis = (jj <= qi + PMEM);
            if (vis) {
                float s0 = 0.f, s1 = 0.f, s2 = 0.f, s3 = 0.f;
                #pragma unroll
                for (int dd = 0; dd < 16; dd++) {
                    float4 kk = sK[j * 16 + dd];
                    float4 qq = q4[dd];
                    s0 = fmaf(qq.x, kk.x, s0);
                    s1 = fmaf(qq.y, kk.y, s1);
                    s2 = fmaf(qq.z, kk.z, s2);
                    s3 = fmaf(qq.w, kk.w, s3);
                }
                float sc = (s0 + s1) + (s2 + s3);
                sc *= 0.125f;
                if (sc > mrun) {
                    float c = __expf(mrun - sc);
                    lrun *= c;
                    #pragma unroll
                    for (int dd = 0; dd < 16; dd++) {
                        o4[dd].x *= c; o4[dd].y *= c; o4[dd].z *= c; o4[dd].w *= c;
                    }
                    mrun = sc;
                }
                float p = __expf(sc - mrun);
                lrun += p;
                #pragma unroll
                for (int dd = 0; dd < 16; dd++) {
                    float4 vv = sV[j * 16 + dd];
                    o4[dd].x = fmaf(p, vv.x, o4[dd].x);
                    o4[dd].y = fmaf(p, vv.y, o4[dd].y);
                    o4[dd].z = fmaf(p, vv.z, o4[dd].z);
                    o4[dd].w = fmaf(p, vv.w, o4[dd].w);
                }
            }
        }
        __syncthreads();
    }

    float invl = 1.0f / lrun;
    float4* op = (float4*)(AO + (size_t)(bw * SEG + qi) * DIM + h * DH);
    #pragma unroll
    for (int dd = 0; dd < 16; dd++) {
        float4 o = o4[dd];
        o.x *= invl; o.y *= invl; o.z *= invl; o.w *= invl;
        op[dd] = o;
    }
}

// ---------------- launch ----------------
extern "C" void kernel_launch(void* const* d_in, const int* in_sizes, int n_in,
                              void* d_out, int out_size) {
    const float* seq   = (const float*)d_in[0];
    const float* g     = (const float*)d_in[1];
    const float* w_qkv = (const float*)d_in[2];
    const float* w_out = (const float*)d_in[3];
    const float* pm    = (const float*)d_in[4];
    float* out = (float*)d_out;

    float *xn, *qkv, *q, *k, *v, *ao;
    cudaGetSymbolAddress((void**)&xn,  g_xn);
    cudaGetSymbolAddress((void**)&qkv, g_qkv);
    cudaGetSymbolAddress((void**)&q,   g_q);
    cudaGetSymbolAddress((void**)&k,   g_k);
    cudaGetSymbolAddress((void**)&v,   g_v);
    cudaGetSymbolAddress((void**)&ao,  g_ao);

    rmsnorm_kernel<<<ROWS, 256>>>(seq, g, xn);
    sgemm_tf32<<<dim3(3 * DIM / BN, ROWS / BM), 256>>>(xn, w_qkv, qkv, ROWS, 3 * DIM, DIM);
    pm_fill<<<BW * HEADS, 1024>>>(pm, k, v);
    rope_scatter<<<ROWS, 512>>>(qkv, q, k, v);
    attn_kernel<<<BW * HEADS * 2, 256>>>(q, k, v, ao);
    sgemm_tf32<<<dim3(DIM / BN, ROWS / BM), 256>>>(ao, w_out, out, ROWS, DIM, DIM);
}

// round 3
// speedup vs baseline: 2.9825x; 1.4558x over previous
#include <cuda_runtime.h>
#include <math.h>

#define DIM    1024
#define HEADS  16
#define DH     64
#define SEG    512
#define PMEM   16
#define BATCH  2
#define NSEQ   4096
#define WSEG   (NSEQ / SEG)       // 8
#define BW     (BATCH * WSEG)     // 16
#define ROWS   (BATCH * NSEQ)     // 8192
#define KV     (SEG + PMEM)       // 528
#define RMS_EPS 1.1920929e-07f

// ---------------- scratch (no cudaMalloc allowed) ----------------
__device__ float g_xn [(size_t)ROWS * DIM];
__device__ float g_qkv[(size_t)ROWS * 3 * DIM];
__device__ float g_q  [(size_t)BW * HEADS * SEG * DH];
__device__ float g_k  [(size_t)BW * HEADS * KV  * DH];
__device__ float g_v  [(size_t)BW * HEADS * KV  * DH];
__device__ float g_ao [(size_t)ROWS * DIM];

// ---------------- helpers ----------------
__device__ __forceinline__ float t32(float f) {
    unsigned r;
    asm("cvt.rna.tf32.f32 %0, %1;" : "=r"(r) : "f"(f));
    return __uint_as_float(r);
}

// exp2 via FFMA-only poly (no MUFU). y <= ~0.
__device__ __forceinline__ float exp2p(float y) {
    y = fmaxf(y, -126.0f);
    float z = y + 12582912.0f;              // round-to-nearest int in mantissa
    int   n = __float_as_int(z) - 0x4B400000;
    float f = y - (z - 12582912.0f);        // f in [-0.5, 0.5]
    float p = 1.33336e-3f;
    p = fmaf(p, f, 9.61813e-3f);
    p = fmaf(p, f, 5.55041e-2f);
    p = fmaf(p, f, 2.40226502e-1f);
    p = fmaf(p, f, 6.93147182e-1f);
    p = fmaf(p, f, 1.0f);
    return p * __int_as_float((n + 127) << 23);
}

__device__ __forceinline__ void mma_tf32(float c[4], float a0, float a1, float a2, float a3,
                                         float b0, float b1) {
    asm volatile(
        "mma.sync.aligned.m16n8k8.row.col.f32.tf32.tf32.f32 "
        "{%0,%1,%2,%3}, {%4,%5,%6,%7}, {%8,%9}, {%0,%1,%2,%3};"
        : "+f"(c[0]), "+f"(c[1]), "+f"(c[2]), "+f"(c[3])
        : "r"(__float_as_uint(a0)), "r"(__float_as_uint(a1)),
          "r"(__float_as_uint(a2)), "r"(__float_as_uint(a3)),
          "r"(__float_as_uint(b0)), "r"(__float_as_uint(b1)));
}

// ---------------- RMSNorm ----------------
__global__ __launch_bounds__(256) void rmsnorm_kernel(const float* __restrict__ seq,
                                                      const float* __restrict__ g,
                                                      float* __restrict__ xn) {
    int row = blockIdx.x;
    int tid = threadIdx.x;
    const float4* in = (const float4*)(seq + (size_t)row * DIM);
    float4 v = in[tid];
    float ss = v.x * v.x + v.y * v.y + v.z * v.z + v.w * v.w;
    #pragma unroll
    for (int o = 16; o; o >>= 1) ss += __shfl_xor_sync(0xFFFFFFFFu, ss, o);
    __shared__ float wsum[8];
    __shared__ float srms;
    if ((tid & 31) == 0) wsum[tid >> 5] = ss;
    __syncthreads();
    if (tid == 0) {
        float t = 0.f;
        #pragma unroll
        for (int i = 0; i < 8; i++) t += wsum[i];
        srms = rsqrtf(t * (1.0f / DIM) + RMS_EPS);
    }
    __syncthreads();
    float r = srms;
    float4 gv = ((const float4*)g)[tid];
    float4 o;
    o.x = v.x * r * gv.x; o.y = v.y * r * gv.y;
    o.z = v.z * r * gv.z; o.w = v.w * r * gv.w;
    ((float4*)(xn + (size_t)row * DIM))[tid] = o;
}

// ---------------- TF32 tensor-core GEMM: C[M,N] = A[M,K] * B[N,K]^T ----------------
#define BM 128
#define BN 128
#define KC 32
#define SPAD 36

__global__ __launch_bounds__(256) void sgemm_tf32(const float* __restrict__ A,
                                                  const float* __restrict__ Bm,
                                                  float* __restrict__ C,
                                                  int M, int Nn, int K) {
    __shared__ float As[BM][SPAD];
    __shared__ float Bs[BN][SPAD];

    int tid = threadIdx.x;
    int bm = blockIdx.y * BM;
    int bn = blockIdx.x * BN;

    int wid  = tid >> 5;
    int lane = tid & 31;
    int warp_m = (wid & 3) * 32;
    int warp_n = (wid >> 2) * 64;
    int grp = lane >> 2;
    int qid = lane & 3;

    int lrow = tid >> 3;
    int lc4  = tid & 7;

    const float* Ag = A  + (size_t)(bm + lrow) * K + lc4 * 4;
    const float* Bg = Bm + (size_t)(bn + lrow) * K + lc4 * 4;

    float c[2][8][4];
    #pragma unroll
    for (int i = 0; i < 2; i++)
        #pragma unroll
        for (int j = 0; j < 8; j++)
            #pragma unroll
            for (int u = 0; u < 4; u++) c[i][j][u] = 0.f;

    float4 ra[4], rb[4];
    #pragma unroll
    for (int i = 0; i < 4; i++) {
        ra[i] = *(const float4*)(Ag + (size_t)(32 * i) * K);
        rb[i] = *(const float4*)(Bg + (size_t)(32 * i) * K);
    }

    for (int k0 = 0; k0 < K; k0 += KC) {
        #pragma unroll
        for (int i = 0; i < 4; i++) {
            float4 a = ra[i], b = rb[i];
            a.x = t32(a.x); a.y = t32(a.y); a.z = t32(a.z); a.w = t32(a.w);
            b.x = t32(b.x); b.y = t32(b.y); b.z = t32(b.z); b.w = t32(b.w);
            *(float4*)&As[lrow + 32 * i][lc4 * 4] = a;
            *(float4*)&Bs[lrow + 32 * i][lc4 * 4] = b;
        }
        __syncthreads();

        if (k0 + KC < K) {
            #pragma unroll
            for (int i = 0; i < 4; i++) {
                ra[i] = *(const float4*)(Ag + (size_t)(32 * i) * K + k0 + KC);
                rb[i] = *(const float4*)(Bg + (size_t)(32 * i) * K + k0 + KC);
            }
        }

        #pragma unroll
        for (int ks = 0; ks < KC; ks += 8) {
            float af[2][4];
            #pragma unroll
            for (int mf = 0; mf < 2; mf++) {
                int row = warp_m + mf * 16 + grp;
                af[mf][0] = As[row    ][ks + qid    ];
                af[mf][1] = As[row + 8][ks + qid    ];
                af[mf][2] = As[row    ][ks + qid + 4];
                af[mf][3] = As[row + 8][ks + qid + 4];
            }
            #pragma unroll
            for (int nf = 0; nf < 8; nf++) {
                int n = warp_n + nf * 8 + grp;
                float b0 = Bs[n][ks + qid];
                float b1 = Bs[n][ks + qid + 4];
                mma_tf32(c[0][nf], af[0][0], af[0][1], af[0][2], af[0][3], b0, b1);
                mma_tf32(c[1][nf], af[1][0], af[1][1], af[1][2], af[1][3], b0, b1);
            }
        }
        __syncthreads();
    }

    #pragma unroll
    for (int mf = 0; mf < 2; mf++) {
        int row0 = bm + warp_m + mf * 16 + grp;
        #pragma unroll
        for (int nf = 0; nf < 8; nf++) {
            int col = bn + warp_n + nf * 8 + qid * 2;
            *(float2*)(C + (size_t)row0 * Nn + col)       = make_float2(c[mf][nf][0], c[mf][nf][1]);
            *(float2*)(C + (size_t)(row0 + 8) * Nn + col) = make_float2(c[mf][nf][2], c[mf][nf][3]);
        }
    }
}

// ---------------- persistent-memory prepend ----------------
__global__ __launch_bounds__(1024) void pm_fill(const float* __restrict__ pm,
                                                float* __restrict__ k,
                                                float* __restrict__ v) {
    int bwh = blockIdx.x;
    int h = bwh & 15;
    int t = threadIdx.x;
    int p = t >> 6;
    int d = t & 63;
    float kv_ = pm[((size_t)h * PMEM + p) * DH + d];
    float vv_ = pm[(size_t)HEADS * PMEM * DH + ((size_t)h * PMEM + p) * DH + d];
    k[((size_t)bwh * KV + p) * DH + d] = kv_;
    v[((size_t)bwh * KV + p) * DH + d] = vv_;
}

// ---------------- RoPE + reshape + segment scatter ----------------
__global__ __launch_bounds__(512) void rope_scatter(const float* __restrict__ qkv,
                                                    float* __restrict__ q,
                                                    float* __restrict__ k,
                                                    float* __restrict__ v) {
    int m = blockIdx.x;
    int b = m >> 12;
    int npos = m & 4095;
    int t = threadIdx.x;
    int h = t >> 5;
    int d = (t & 31) * 2;

    const float* row = qkv + (size_t)m * 3 * DIM;
    float2 qv = *(const float2*)(row + h * DH + d);
    float2 kv2 = *(const float2*)(row + DIM + h * DH + d);
    float2 vv = *(const float2*)(row + 2 * DIM + h * DH + d);

    float inv = 1.0f / powf(10000.0f, (float)d * (1.0f / 64.0f));
    float ang = (float)npos * inv;
    float sn, cs;
    sincosf(ang, &sn, &cs);
    float2 qr, kr;
    qr.x = qv.x * cs - qv.y * sn;  qr.y = qv.y * cs + qv.x * sn;
    kr.x = kv2.x * cs - kv2.y * sn; kr.y = kv2.y * cs + kv2.x * sn;

    int w = npos >> 9;
    int sidx = npos & 511;
    int bwh = (b * WSEG + w) * HEADS + h;
    *(float2*)(q + ((size_t)bwh * SEG + sidx) * DH + d) = qr;
    *(float2*)(k + ((size_t)bwh * KV + PMEM + sidx) * DH + d) = kr;
    *(float2*)(v + ((size_t)bwh * KV + PMEM + sidx) * DH + d) = vv;
}

// ---------------- tensor-core flash attention ----------------
// grid (4 qtiles, 256 bwh), 256 threads = 8 warps x 16 q-rows. KV tiles of 64.
#define KSTR 68   // smem row stride (floats): conflict-free frag loads

__global__ __launch_bounds__(256) void attn_tc(const float* __restrict__ Q,
                                               const float* __restrict__ K,
                                               const float* __restrict__ V,
                                               float* __restrict__ AO) {
    __shared__ float sK [64][KSTR];
    __shared__ float sVt[64][KSTR];

    const int tid  = threadIdx.x;
    const int wid  = tid >> 5;
    const int lane = tid & 31;
    const int grp  = lane >> 2;
    const int qid  = lane & 3;
    const int bwh  = blockIdx.y;
    const int q0   = blockIdx.x * 128;
    const int wq0  = q0 + wid * 16;

    const float* Qb = Q + (size_t)bwh * SEG * DH;
    const float* Kb = K + (size_t)bwh * KV * DH;
    const float* Vb = V + (size_t)bwh * KV * DH;

    const int r  = tid >> 2;        // staging row 0..63
    const int c4 = tid & 3;         // staging quarter

    // ---- Q fragments (pre-scaled into log2 domain), staged via sK in 2 passes ----
    const float QSC = 0.125f * 1.4426950408889634f;
    float aq[8][4];
    #pragma unroll
    for (int pass = 0; pass < 2; pass++) {
        const float* qg = Qb + (size_t)(q0 + pass * 64 + r) * DH + c4 * 16;
        #pragma unroll
        for (int u = 0; u < 4; u++) {
            float4 x = *(const float4*)(qg + u * 4);
            x.x = t32(x.x * QSC); x.y = t32(x.y * QSC);
            x.z = t32(x.z * QSC); x.w = t32(x.w * QSC);
            *(float4*)&sK[r][c4 * 16 + u * 4] = x;
        }
        __syncthreads();
        if ((wid >> 2) == pass) {
            int lr = (wid & 3) * 16 + grp;
            #pragma unroll
            for (int ks = 0; ks < 8; ks++) {
                aq[ks][0] = sK[lr    ][ks * 8 + qid    ];
                aq[ks][1] = sK[lr + 8][ks * 8 + qid    ];
                aq[ks][2] = sK[lr    ][ks * 8 + qid + 4];
                aq[ks][3] = sK[lr + 8][ks * 8 + qid + 4];
            }
        }
        __syncthreads();
    }

    float o[8][4];
    #pragma unroll
    for (int nf = 0; nf < 8; nf++)
        #pragma unroll
        for (int u = 0; u < 4; u++) o[nf][u] = 0.f;
    float m0 = -1e30f, m1 = -1e30f, l0 = 0.f, l1 = 0.f;

    int jmax = q0 + 128 + PMEM;
    if (jmax > KV) jmax = KV;
    int ntiles = (jmax + 63) >> 6;

    for (int t = 0; t < ntiles; t++) {
        int jj0 = t << 6;
        // ---- stage K (tf32) and V transposed (tf32) ----
        {
            int jj = jj0 + r;
            if (jj < KV) {
                const float* kg = Kb + (size_t)jj * DH + c4 * 16;
                const float* vg = Vb + (size_t)jj * DH + c4 * 16;
                #pragma unroll
                for (int u = 0; u < 4; u++) {
                    float4 kx = *(const float4*)(kg + u * 4);
                    kx.x = t32(kx.x); kx.y = t32(kx.y); kx.z = t32(kx.z); kx.w = t32(kx.w);
                    *(float4*)&sK[r][c4 * 16 + u * 4] = kx;
                    float4 vx = *(const float4*)(vg + u * 4);
                    int db = c4 * 16 + u * 4;
                    sVt[db + 0][r] = t32(vx.x);
                    sVt[db + 1][r] = t32(vx.y);
                    sVt[db + 2][r] = t32(vx.z);
                    sVt[db + 3][r] = t32(vx.w);
                }
            } else {
                #pragma unroll
                for (int u = 0; u < 4; u++) {
                    *(float4*)&sK[r][c4 * 16 + u * 4] = make_float4(0.f, 0.f, 0.f, 0.f);
                    int db = c4 * 16 + u * 4;
                    sVt[db + 0][r] = 0.f; sVt[db + 1][r] = 0.f;
                    sVt[db + 2][r] = 0.f; sVt[db + 3][r] = 0.f;
                }
            }
        }
        __syncthreads();

        if (jj0 <= wq0 + 15 + PMEM) {          // warp has visible keys in this tile
            // ---- S = Q K^T (log2 domain) ----
            float c[8][4];
            #pragma unroll
            for (int nf = 0; nf < 8; nf++)
                #pragma unroll
                for (int u = 0; u < 4; u++) c[nf][u] = 0.f;

            #pragma unroll
            for (int ks = 0; ks < 8; ks++) {
                #pragma unroll
                for (int nf = 0; nf < 8; nf++) {
                    float b0 = sK[nf * 8 + grp][ks * 8 + qid    ];
                    float b1 = sK[nf * 8 + grp][ks * 8 + qid + 4];
                    mma_tf32(c[nf], aq[ks][0], aq[ks][1], aq[ks][2], aq[ks][3], b0, b1);
                }
            }

            // ---- causal mask (also covers zero-padded keys past KV) ----
            if (jj0 + 63 > wq0 + PMEM) {
                int r0 = wq0 + grp, r1 = r0 + 8;
                #pragma unroll
                for (int nf = 0; nf < 8; nf++) {
                    int j0 = jj0 + nf * 8 + 2 * qid;
                    if (j0     - PMEM > r0) c[nf][0] = -1e30f;
                    if (j0 + 1 - PMEM > r0) c[nf][1] = -1e30f;
                    if (j0     - PMEM > r1) c[nf][2] = -1e30f;
                    if (j0 + 1 - PMEM > r1) c[nf][3] = -1e30f;
                }
            }

            // ---- online softmax (base-2, FFMA-only exp) ----
            float mt0 = -1e30f, mt1 = -1e30f;
            #pragma unroll
            for (int nf = 0; nf < 8; nf++) {
                mt0 = fmaxf(mt0, fmaxf(c[nf][0], c[nf][1]));
                mt1 = fmaxf(mt1, fmaxf(c[nf][2], c[nf][3]));
            }
            mt0 = fmaxf(mt0, __shfl_xor_sync(0xFFFFFFFFu, mt0, 1));
            mt0 = fmaxf(mt0, __shfl_xor_sync(0xFFFFFFFFu, mt0, 2));
            mt1 = fmaxf(mt1, __shfl_xor_sync(0xFFFFFFFFu, mt1, 1));
            mt1 = fmaxf(mt1, __shfl_xor_sync(0xFFFFFFFFu, mt1, 2));

            float nm0 = fmaxf(m0, mt0), nm1 = fmaxf(m1, mt1);
            float f0 = exp2p(m0 - nm0), f1 = exp2p(m1 - nm1);
            m0 = nm0; m1 = nm1;
            l0 *= f0; l1 *= f1;
            #pragma unroll
            for (int nf = 0; nf < 8; nf++) {
                o[nf][0] *= f0; o[nf][1] *= f0;
                o[nf][2] *= f1; o[nf][3] *= f1;
            }

            float s0 = 0.f, s1 = 0.f;
            #pragma unroll
            for (int nf = 0; nf < 8; nf++) {
                float p00 = t32(exp2p(c[nf][0] - m0));
                float p01 = t32(exp2p(c[nf][1] - m0));
                float p10 = t32(exp2p(c[nf][2] - m1));
                float p11 = t32(exp2p(c[nf][3] - m1));
                c[nf][0] = p00; c[nf][1] = p01; c[nf][2] = p10; c[nf][3] = p11;
                s0 += p00 + p01; s1 += p10 + p11;
            }
            s0 += __shfl_xor_sync(0xFFFFFFFFu, s0, 1);
            s0 += __shfl_xor_sync(0xFFFFFFFFu, s0, 2);
            s1 += __shfl_xor_sync(0xFFFFFFFFu, s1, 1);
            s1 += __shfl_xor_sync(0xFFFFFFFFu, s1, 2);
            l0 += s0; l1 += s1;

            // ---- O += P V : convert C-frag layout to A-frag via quad shuffles ----
            int qbase = lane & ~3;
            int qs0 = qbase | (qid >> 1);
            int qs2 = qbase | (2 + (qid >> 1));
            bool hi = (qid & 1);
            #pragma unroll
            for (int kk = 0; kk < 8; kk++) {
                float x0 = __shfl_sync(0xFFFFFFFFu, c[kk][0], qs0);
                float x1 = __shfl_sync(0xFFFFFFFFu, c[kk][1], qs0);
                float a0 = hi ? x1 : x0;
                float z0 = __shfl_sync(0xFFFFFFFFu, c[kk][2], qs0);
                float z1 = __shfl_sync(0xFFFFFFFFu, c[kk][3], qs0);
                float a1 = hi ? z1 : z0;
                float x2 = __shfl_sync(0xFFFFFFFFu, c[kk][0], qs2);
                float x3 = __shfl_sync(0xFFFFFFFFu, c[kk][1], qs2);
                float a2 = hi ? x3 : x2;
                float z2 = __shfl_sync(0xFFFFFFFFu, c[kk][2], qs2);
                float z3 = __shfl_sync(0xFFFFFFFFu, c[kk][3], qs2);
                float a3 = hi ? z3 : z2;
                #pragma unroll
                for (int nf = 0; nf < 8; nf++) {
                    float b0 = sVt[nf * 8 + grp][kk * 8 + qid    ];
                    float b1 = sVt[nf * 8 + grp][kk * 8 + qid + 4];
                    mma_tf32(o[nf], a0, a1, a2, a3, b0, b1);
                }
            }
        }
        __syncthreads();
    }

    // ---- epilogue ----
    float inv0 = 1.0f / l0, inv1 = 1.0f / l1;
    int bw = bwh >> 4, h = bwh & 15;
    int r0 = wq0 + grp, r1 = r0 + 8;
    float* out0 = AO + (size_t)(bw * SEG + r0) * DIM + h * DH;
    float* out1 = AO + (size_t)(bw * SEG + r1) * DIM + h * DH;
    #pragma unroll
    for (int nf = 0; nf < 8; nf++) {
        int col = nf * 8 + 2 * qid;
        *(float2*)(out0 + col) = make_float2(o[nf][0] * inv0, o[nf][1] * inv0);
        *(float2*)(out1 + col) = make_float2(o[nf][2] * inv1, o[nf][3] * inv1);
    }
}

// ---------------- launch ----------------
extern "C" void kernel_launch(void* const* d_in, const int* in_sizes, int n_in,
                              void* d_out, int out_size) {
    const float* seq   = (const float*)d_in[0];
    const float* g     = (const float*)d_in[1];
    const float* w_qkv = (const float*)d_in[2];
    const float* w_out = (const float*)d_in[3];
    const float* pm    = (const float*)d_in[4];
    float* out = (float*)d_out;

    float *xn, *qkv, *q, *k, *v, *ao;
    cudaGetSymbolAddress((void**)&xn,  g_xn);
    cudaGetSymbolAddress((void**)&qkv, g_qkv);
    cudaGetSymbolAddress((void**)&q,   g_q);
    cudaGetSymbolAddress((void**)&k,   g_k);
    cudaGetSymbolAddress((void**)&v,   g_v);
    cudaGetSymbolAddress((void**)&ao,  g_ao);

    rmsnorm_kernel<<<ROWS, 256>>>(seq, g, xn);
    sgemm_tf32<<<dim3(3 * DIM / BN, ROWS / BM), 256>>>(xn, w_qkv, qkv, ROWS, 3 * DIM, DIM);
    pm_fill<<<BW * HEADS, 1024>>>(pm, k, v);
    rope_scatter<<<ROWS, 512>>>(qkv, q, k, v);
    attn_tc<<<dim3(4, BW * HEADS), 256>>>(q, k, v, ao);
    sgemm_tf32<<<dim3(DIM / BN, ROWS / BM), 256>>>(ao, w_out, out, ROWS, DIM, DIM);
}

// round 6
// speedup vs baseline: 4.3042x; 1.4432x over previous
#include <cuda_runtime.h>
#include <cuda_fp16.h>
#include <math.h>

#define DIM    1024
#define HEADS  16
#define DH     64
#define SEG    512
#define PMEM   16
#define BATCH  2
#define NSEQ   4096
#define WSEG   (NSEQ / SEG)       // 8
#define BW     (BATCH * WSEG)     // 16
#define ROWS   (BATCH * NSEQ)     // 8192
#define KV     (SEG + PMEM)       // 528
#define RMS_EPS 1.1920929e-07f

// ---------------- scratch (no cudaMalloc allowed) ----------------
__device__ __half g_xnh[(size_t)ROWS * DIM];           // RMSNorm output (half)
__device__ __half g_whq[(size_t)3 * DIM * DIM];        // w_qkv half
__device__ __half g_who[(size_t)DIM * DIM];            // w_out half
__device__ float  g_qkv[(size_t)ROWS * 3 * DIM];       // QKV projection (fp32)
__device__ float  g_q  [(size_t)BW * HEADS * SEG * DH];
__device__ float  g_k  [(size_t)BW * HEADS * KV  * DH];
__device__ float  g_v  [(size_t)BW * HEADS * KV  * DH];
__device__ __half g_aoh[(size_t)ROWS * DIM];           // attention out (half)

// ---------------- helpers ----------------
__device__ __forceinline__ float t32(float f) {
    unsigned r;
    asm("cvt.rna.tf32.f32 %0, %1;" : "=r"(r) : "f"(f));
    return __uint_as_float(r);
}

// exp2 via FFMA-only poly (no MUFU). y <= ~0.
__device__ __forceinline__ float exp2p(float y) {
    y = fmaxf(y, -126.0f);
    float z = y + 12582912.0f;
    int   n = __float_as_int(z) - 0x4B400000;
    float f = y - (z - 12582912.0f);
    float p = 1.33336e-3f;
    p = fmaf(p, f, 9.61813e-3f);
    p = fmaf(p, f, 5.55041e-2f);
    p = fmaf(p, f, 2.40226502e-1f);
    p = fmaf(p, f, 6.93147182e-1f);
    p = fmaf(p, f, 1.0f);
    return p * __int_as_float((n + 127) << 23);
}

__device__ __forceinline__ void mma_tf32(float c[4], float a0, float a1, float a2, float a3,
                                         float b0, float b1) {
    asm volatile(
        "mma.sync.aligned.m16n8k8.row.col.f32.tf32.tf32.f32 "
        "{%0,%1,%2,%3}, {%4,%5,%6,%7}, {%8,%9}, {%0,%1,%2,%3};"
        : "+f"(c[0]), "+f"(c[1]), "+f"(c[2]), "+f"(c[3])
        : "r"(__float_as_uint(a0)), "r"(__float_as_uint(a1)),
          "r"(__float_as_uint(a2)), "r"(__float_as_uint(a3)),
          "r"(__float_as_uint(b0)), "r"(__float_as_uint(b1)));
}

__device__ __forceinline__ void mma_f16(float c[4], unsigned a0, unsigned a1, unsigned a2,
                                        unsigned a3, unsigned b0, unsigned b1) {
    asm volatile(
        "mma.sync.aligned.m16n8k16.row.col.f32.f16.f16.f32 "
        "{%0,%1,%2,%3}, {%4,%5,%6,%7}, {%8,%9}, {%0,%1,%2,%3};"
        : "+f"(c[0]), "+f"(c[1]), "+f"(c[2]), "+f"(c[3])
        : "r"(a0), "r"(a1), "r"(a2), "r"(a3), "r"(b0), "r"(b1));
}

// ---------------- weight fp32 -> fp16 ----------------
__global__ __launch_bounds__(256) void f2h_kernel(const float* __restrict__ s,
                                                  __half* __restrict__ d, int n4) {
    int i = blockIdx.x * 256 + threadIdx.x;
    if (i < n4) {
        float4 v = ((const float4*)s)[i];
        __half2 h0 = __floats2half2_rn(v.x, v.y);
        __half2 h1 = __floats2half2_rn(v.z, v.w);
        ((uint2*)d)[i] = make_uint2(*(unsigned*)&h0, *(unsigned*)&h1);
    }
}

// ---------------- RMSNorm (fp16 out) ----------------
__global__ __launch_bounds__(256) void rmsnorm_kernel(const float* __restrict__ seq,
                                                      const float* __restrict__ g,
                                                      __half* __restrict__ xnh) {
    int row = blockIdx.x;
    int tid = threadIdx.x;
    const float4* in = (const float4*)(seq + (size_t)row * DIM);
    float4 v = in[tid];
    float ss = v.x * v.x + v.y * v.y + v.z * v.z + v.w * v.w;
    #pragma unroll
    for (int o = 16; o; o >>= 1) ss += __shfl_xor_sync(0xFFFFFFFFu, ss, o);
    __shared__ float wsum[8];
    __shared__ float srms;
    if ((tid & 31) == 0) wsum[tid >> 5] = ss;
    __syncthreads();
    if (tid == 0) {
        float t = 0.f;
        #pragma unroll
        for (int i = 0; i < 8; i++) t += wsum[i];
        srms = rsqrtf(t * (1.0f / DIM) + RMS_EPS);
    }
    __syncthreads();
    float r = srms;
    float4 gv = ((const float4*)g)[tid];
    __half2 h0 = __floats2half2_rn(v.x * r * gv.x, v.y * r * gv.y);
    __half2 h1 = __floats2half2_rn(v.z * r * gv.z, v.w * r * gv.w);
    ((uint2*)(xnh + (size_t)row * DIM))[tid] = make_uint2(*(unsigned*)&h0, *(unsigned*)&h1);
}

// ---------------- FP16 tensor-core GEMM: C[M,N] = A[M,K] * B[N,K]^T ----------------
// CTA 128x128, KC=64, 8 warps (4m x 2n), warp tile 32x64, mma.m16n8k16.f16
#define BM 128
#define BN 128
#define KC 64
#define HS 72     // smem row stride in halves: row*36 words => row*4 mod 32 banks

__global__ __launch_bounds__(256) void hgemm(const __half* __restrict__ A,
                                             const __half* __restrict__ Bm,
                                             float* __restrict__ C,
                                             int M, int Nn, int K) {
    __shared__ __half As[BM][HS];
    __shared__ __half Bs[BN][HS];

    int tid = threadIdx.x;
    int bm = blockIdx.y * BM;
    int bn = blockIdx.x * BN;

    int wid  = tid >> 5;
    int lane = tid & 31;
    int warp_m = (wid & 3) * 32;
    int warp_n = (wid >> 2) * 64;
    int grp = lane >> 2;
    int qid = lane & 3;

    int lrow = tid >> 2;          // 0..63
    int lc   = (tid & 3) * 16;    // half index 0,16,32,48

    const __half* Ag = A  + (size_t)(bm + lrow) * K + lc;
    const __half* Bg = Bm + (size_t)(bn + lrow) * K + lc;

    float c[2][8][4];
    #pragma unroll
    for (int i = 0; i < 2; i++)
        #pragma unroll
        for (int j = 0; j < 8; j++)
            #pragma unroll
            for (int u = 0; u < 4; u++) c[i][j][u] = 0.f;

    uint4 ra[2][2], rb[2][2];
    #pragma unroll
    for (int i = 0; i < 2; i++) {
        ra[i][0] = *(const uint4*)(Ag + (size_t)(64 * i) * K);
        ra[i][1] = *(const uint4*)(Ag + (size_t)(64 * i) * K + 8);
        rb[i][0] = *(const uint4*)(Bg + (size_t)(64 * i) * K);
        rb[i][1] = *(const uint4*)(Bg + (size_t)(64 * i) * K + 8);
    }

    for (int k0 = 0; k0 < K; k0 += KC) {
        #pragma unroll
        for (int i = 0; i < 2; i++) {
            *(uint4*)&As[lrow + 64 * i][lc]     = ra[i][0];
            *(uint4*)&As[lrow + 64 * i][lc + 8] = ra[i][1];
            *(uint4*)&Bs[lrow + 64 * i][lc]     = rb[i][0];
            *(uint4*)&Bs[lrow + 64 * i][lc + 8] = rb[i][1];
        }
        __syncthreads();

        if (k0 + KC < K) {
            #pragma unroll
            for (int i = 0; i < 2; i++) {
                ra[i][0] = *(const uint4*)(Ag + (size_t)(64 * i) * K + k0 + KC);
                ra[i][1] = *(const uint4*)(Ag + (size_t)(64 * i) * K + k0 + KC + 8);
                rb[i][0] = *(const uint4*)(Bg + (size_t)(64 * i) * K + k0 + KC);
                rb[i][1] = *(const uint4*)(Bg + (size_t)(64 * i) * K + k0 + KC + 8);
            }
        }

        #pragma unroll
        for (int ks = 0; ks < KC; ks += 16) {
            unsigned af[2][4];
            #pragma unroll
            for (int mf = 0; mf < 2; mf++) {
                int row = warp_m + mf * 16 + grp;
                af[mf][0] = *(const unsigned*)&As[row    ][ks + 2 * qid    ];
                af[mf][1] = *(const unsigned*)&As[row + 8][ks + 2 * qid    ];
                af[mf][2] = *(const unsigned*)&As[row    ][ks + 2 * qid + 8];
                af[mf][3] = *(const unsigned*)&As[row + 8][ks + 2 * qid + 8];
            }
            #pragma unroll
            for (int nf = 0; nf < 8; nf++) {
                int n = warp_n + nf * 8 + grp;
                unsigned b0 = *(const unsigned*)&Bs[n][ks + 2 * qid    ];
                unsigned b1 = *(const unsigned*)&Bs[n][ks + 2 * qid + 8];
                mma_f16(c[0][nf], af[0][0], af[0][1], af[0][2], af[0][3], b0, b1);
                mma_f16(c[1][nf], af[1][0], af[1][1], af[1][2], af[1][3], b0, b1);
            }
        }
        __syncthreads();
    }

    #pragma unroll
    for (int mf = 0; mf < 2; mf++) {
        int row0 = bm + warp_m + mf * 16 + grp;
        #pragma unroll
        for (int nf = 0; nf < 8; nf++) {
            int col = bn + warp_n + nf * 8 + qid * 2;
            *(float2*)(C + (size_t)row0 * Nn + col)       = make_float2(c[mf][nf][0], c[mf][nf][1]);
            *(float2*)(C + (size_t)(row0 + 8) * Nn + col) = make_float2(c[mf][nf][2], c[mf][nf][3]);
        }
    }
}

// ---------------- persistent-memory prepend ----------------
__global__ __launch_bounds__(1024) void pm_fill(const float* __restrict__ pm,
                                                float* __restrict__ k,
                                                float* __restrict__ v) {
    int bwh = blockIdx.x;
    int h = bwh & 15;
    int t = threadIdx.x;
    int p = t >> 6;
    int d = t & 63;
    float kv_ = pm[((size_t)h * PMEM + p) * DH + d];
    float vv_ = pm[(size_t)HEADS * PMEM * DH + ((size_t)h * PMEM + p) * DH + d];
    k[((size_t)bwh * KV + p) * DH + d] = kv_;
    v[((size_t)bwh * KV + p) * DH + d] = vv_;
}

// ---------------- RoPE + reshape + segment scatter ----------------
__global__ __launch_bounds__(512) void rope_scatter(const float* __restrict__ qkv,
                                                    float* __restrict__ q,
                                                    float* __restrict__ k,
                                                    float* __restrict__ v) {
    int m = blockIdx.x;
    int b = m >> 12;
    int npos = m & 4095;
    int t = threadIdx.x;
    int h = t >> 5;
    int d = (t & 31) * 2;

    const float* row = qkv + (size_t)m * 3 * DIM;
    float2 qv = *(const float2*)(row + h * DH + d);
    float2 kv2 = *(const float2*)(row + DIM + h * DH + d);
    float2 vv = *(const float2*)(row + 2 * DIM + h * DH + d);

    float inv = 1.0f / powf(10000.0f, (float)d * (1.0f / 64.0f));
    float ang = (float)npos * inv;
    float sn, cs;
    sincosf(ang, &sn, &cs);
    float2 qr, kr;
    qr.x = qv.x * cs - qv.y * sn;  qr.y = qv.y * cs + qv.x * sn;
    kr.x = kv2.x * cs - kv2.y * sn; kr.y = kv2.y * cs + kv2.x * sn;

    int w = npos >> 9;
    int sidx = npos & 511;
    int bwh = (b * WSEG + w) * HEADS + h;
    *(float2*)(q + ((size_t)bwh * SEG + sidx) * DH + d) = qr;
    *(float2*)(k + ((size_t)bwh * KV + PMEM + sidx) * DH + d) = kr;
    *(float2*)(v + ((size_t)bwh * KV + PMEM + sidx) * DH + d) = vv;
}

// ---------------- tensor-core flash attention (half out) ----------------
#define KSTR 68

__global__ __launch_bounds__(256) void attn_tc(const float* __restrict__ Q,
                                               const float* __restrict__ K,
                                               const float* __restrict__ V,
                                               __half* __restrict__ AO) {
    __shared__ float sK [64][KSTR];
    __shared__ float sVt[64][KSTR];

    const int tid  = threadIdx.x;
    const int wid  = tid >> 5;
    const int lane = tid & 31;
    const int grp  = lane >> 2;
    const int qid  = lane & 3;
    const int bwh  = blockIdx.y;
    const int q0   = blockIdx.x * 128;
    const int wq0  = q0 + wid * 16;

    const float* Qb = Q + (size_t)bwh * SEG * DH;
    const float* Kb = K + (size_t)bwh * KV * DH;
    const float* Vb = V + (size_t)bwh * KV * DH;

    const int r  = tid >> 2;
    const int c4 = tid & 3;

    const float QSC = 0.125f * 1.4426950408889634f;
    float aq[8][4];
    #pragma unroll
    for (int pass = 0; pass < 2; pass++) {
        const float* qg = Qb + (size_t)(q0 + pass * 64 + r) * DH + c4 * 16;
        #pragma unroll
        for (int u = 0; u < 4; u++) {
            float4 x = *(const float4*)(qg + u * 4);
            x.x = t32(x.x * QSC); x.y = t32(x.y * QSC);
            x.z = t32(x.z * QSC); x.w = t32(x.w * QSC);
            *(float4*)&sK[r][c4 * 16 + u * 4] = x;
        }
        __syncthreads();
        if ((wid >> 2) == pass) {
            int lr = (wid & 3) * 16 + grp;
            #pragma unroll
            for (int ks = 0; ks < 8; ks++) {
                aq[ks][0] = sK[lr    ][ks * 8 + qid    ];
                aq[ks][1] = sK[lr + 8][ks * 8 + qid    ];
                aq[ks][2] = sK[lr    ][ks * 8 + qid + 4];
                aq[ks][3] = sK[lr + 8][ks * 8 + qid + 4];
            }
        }
        __syncthreads();
    }

    float o[8][4];
    #pragma unroll
    for (int nf = 0; nf < 8; nf++)
        #pragma unroll
        for (int u = 0; u < 4; u++) o[nf][u] = 0.f;
    float m0 = -1e30f, m1 = -1e30f, l0 = 0.f, l1 = 0.f;

    int jmax = q0 + 128 + PMEM;
    if (jmax > KV) jmax = KV;
    int ntiles = (jmax + 63) >> 6;

    for (int t = 0; t < ntiles; t++) {
        int jj0 = t << 6;
        {
            int jj = jj0 + r;
            if (jj < KV) {
                const float* kg = Kb + (size_t)jj * DH + c4 * 16;
                const float* vg = Vb + (size_t)jj * DH + c4 * 16;
                #pragma unroll
                for (int u = 0; u < 4; u++) {
                    float4 kx = *(const float4*)(kg + u * 4);
                    kx.x = t32(kx.x); kx.y = t32(kx.y); kx.z = t32(kx.z); kx.w = t32(kx.w);
                    *(float4*)&sK[r][c4 * 16 + u * 4] = kx;
                    float4 vx = *(const float4*)(vg + u * 4);
                    int db = c4 * 16 + u * 4;
                    sVt[db + 0][r] = t32(vx.x);
                    sVt[db + 1][r] = t32(vx.y);
                    sVt[db + 2][r] = t32(vx.z);
                    sVt[db + 3][r] = t32(vx.w);
                }
            } else {
                #pragma unroll
                for (int u = 0; u < 4; u++) {
                    *(float4*)&sK[r][c4 * 16 + u * 4] = make_float4(0.f, 0.f, 0.f, 0.f);
                    int db = c4 * 16 + u * 4;
                    sVt[db + 0][r] = 0.f; sVt[db + 1][r] = 0.f;
                    sVt[db + 2][r] = 0.f; sVt[db + 3][r] = 0.f;
                }
            }
        }
        __syncthreads();

        if (jj0 <= wq0 + 15 + PMEM) {
            float c[8][4];
            #pragma unroll
            for (int nf = 0; nf < 8; nf++)
                #pragma unroll
                for (int u = 0; u < 4; u++) c[nf][u] = 0.f;

            #pragma unroll
            for (int ks = 0; ks < 8; ks++) {
                #pragma unroll
                for (int nf = 0; nf < 8; nf++) {
                    float b0 = sK[nf * 8 + grp][ks * 8 + qid    ];
                    float b1 = sK[nf * 8 + grp][ks * 8 + qid + 4];
                    mma_tf32(c[nf], aq[ks][0], aq[ks][1], aq[ks][2], aq[ks][3], b0, b1);
                }
            }

            if (jj0 + 63 > wq0 + PMEM) {
                int r0 = wq0 + grp, r1 = r0 + 8;
                #pragma unroll
                for (int nf = 0; nf < 8; nf++) {
                    int j0 = jj0 + nf * 8 + 2 * qid;
                    if (j0     - PMEM > r0) c[nf][0] = -1e30f;
                    if (j0 + 1 - PMEM > r0) c[nf][1] = -1e30f;
                    if (j0     - PMEM > r1) c[nf][2] = -1e30f;
                    if (j0 + 1 - PMEM > r1) c[nf][3] = -1e30f;
                }
            }

            float mt0 = -1e30f, mt1 = -1e30f;
            #pragma unroll
            for (int nf = 0; nf < 8; nf++) {
                mt0 = fmaxf(mt0, fmaxf(c[nf][0], c[nf][1]));
                mt1 = fmaxf(mt1, fmaxf(c[nf][2], c[nf][3]));
            }
            mt0 = fmaxf(mt0, __shfl_xor_sync(0xFFFFFFFFu, mt0, 1));
            mt0 = fmaxf(mt0, __shfl_xor_sync(0xFFFFFFFFu, mt0, 2));
            mt1 = fmaxf(mt1, __shfl_xor_sync(0xFFFFFFFFu, mt1, 1));
            mt1 = fmaxf(mt1, __shfl_xor_sync(0xFFFFFFFFu, mt1, 2));

            float nm0 = fmaxf(m0, mt0), nm1 = fmaxf(m1, mt1);
            float f0 = exp2p(m0 - nm0), f1 = exp2p(m1 - nm1);
            m0 = nm0; m1 = nm1;
            l0 *= f0; l1 *= f1;
            #pragma unroll
            for (int nf = 0; nf < 8; nf++) {
                o[nf][0] *= f0; o[nf][1] *= f0;
                o[nf][2] *= f1; o[nf][3] *= f1;
            }

            float s0 = 0.f, s1 = 0.f;
            #pragma unroll
            for (int nf = 0; nf < 8; nf++) {
                float p00 = t32(exp2p(c[nf][0] - m0));
                float p01 = t32(exp2p(c[nf][1] - m0));
                float p10 = t32(exp2p(c[nf][2] - m1));
                float p11 = t32(exp2p(c[nf][3] - m1));
                c[nf][0] = p00; c[nf][1] = p01; c[nf][2] = p10; c[nf][3] = p11;
                s0 += p00 + p01; s1 += p10 + p11;
            }
            s0 += __shfl_xor_sync(0xFFFFFFFFu, s0, 1);
            s0 += __shfl_xor_sync(0xFFFFFFFFu, s0, 2);
            s1 += __shfl_xor_sync(0xFFFFFFFFu, s1, 1);
            s1 += __shfl_xor_sync(0xFFFFFFFFu, s1, 2);
            l0 += s0; l1 += s1;

            int qbase = lane & ~3;
            int qs0 = qbase | (qid >> 1);
            int qs2 = qbase | (2 + (qid >> 1));
            bool hi = (qid & 1);
            #pragma unroll
            for (int kk = 0; kk < 8; kk++) {
                float x0 = __shfl_sync(0xFFFFFFFFu, c[kk][0], qs0);
                float x1 = __shfl_sync(0xFFFFFFFFu, c[kk][1], qs0);
                float a0 = hi ? x1 : x0;
                float z0 = __shfl_sync(0xFFFFFFFFu, c[kk][2], qs0);
                float z1 = __shfl_sync(0xFFFFFFFFu, c[kk][3], qs0);
                float a1 = hi ? z1 : z0;
                float x2 = __shfl_sync(0xFFFFFFFFu, c[kk][0], qs2);
                float x3 = __shfl_sync(0xFFFFFFFFu, c[kk][1], qs2);
                float a2 = hi ? x3 : x2;
                float z2 = __shfl_sync(0xFFFFFFFFu, c[kk][2], qs2);
                float z3 = __shfl_sync(0xFFFFFFFFu, c[kk][3], qs2);
                float a3 = hi ? z3 : z2;
                #pragma unroll
                for (int nf = 0; nf < 8; nf++) {
                    float b0 = sVt[nf * 8 + grp][kk * 8 + qid    ];
                    float b1 = sVt[nf * 8 + grp][kk * 8 + qid + 4];
                    mma_tf32(o[nf], a0, a1, a2, a3, b0, b1);
                }
            }
        }
        __syncthreads();
    }

    float inv0 = 1.0f / l0, inv1 = 1.0f / l1;
    int bw = bwh >> 4, h = bwh & 15;
    int r0 = wq0 + grp, r1 = r0 + 8;
    __half* out0 = AO + (size_t)(bw * SEG + r0) * DIM + h * DH;
    __half* out1 = AO + (size_t)(bw * SEG + r1) * DIM + h * DH;
    #pragma unroll
    for (int nf = 0; nf < 8; nf++) {
        int col = nf * 8 + 2 * qid;
        __half2 h0 = __floats2half2_rn(o[nf][0] * inv0, o[nf][1] * inv0);
        __half2 h1 = __floats2half2_rn(o[nf][2] * inv1, o[nf][3] * inv1);
        *(unsigned*)(out0 + col) = *(unsigned*)&h0;
        *(unsigned*)(out1 + col) = *(unsigned*)&h1;
    }
}

// ---------------- launch ----------------
extern "C" void kernel_launch(void* const* d_in, const int* in_sizes, int n_in,
                              void* d_out, int out_size) {
    const float* seq   = (const float*)d_in[0];
    const float* g     = (const float*)d_in[1];
    const float* w_qkv = (const float*)d_in[2];
    const float* w_out = (const float*)d_in[3];
    const float* pm    = (const float*)d_in[4];
    float* out = (float*)d_out;

    __half *xnh, *whq, *who, *aoh;
    float *qkv, *q, *k, *v;
    cudaGetSymbolAddress((void**)&xnh, g_xnh);
    cudaGetSymbolAddress((void**)&whq, g_whq);
    cudaGetSymbolAddress((void**)&who, g_who);
    cudaGetSymbolAddress((void**)&qkv, g_qkv);
    cudaGetSymbolAddress((void**)&q,   g_q);
    cudaGetSymbolAddress((void**)&k,   g_k);
    cudaGetSymbolAddress((void**)&v,   g_v);
    cudaGetSymbolAddress((void**)&aoh, g_aoh);

    f2h_kernel<<<(3 * DIM * DIM / 4 + 255) / 256, 256>>>(w_qkv, whq, 3 * DIM * DIM / 4);
    f2h_kernel<<<(DIM * DIM / 4 + 255) / 256, 256>>>(w_out, who, DIM * DIM / 4);
    rmsnorm_kernel<<<ROWS, 256>>>(seq, g, xnh);
    hgemm<<<dim3(3 * DIM / BN, ROWS / BM), 256>>>(xnh, whq, qkv, ROWS, 3 * DIM, DIM);
    pm_fill<<<BW * HEADS, 1024>>>(pm, k, v);
    rope_scatter<<<ROWS, 512>>>(qkv, q, k, v);
    attn_tc<<<dim3(4, BW * HEADS), 256>>>(q, k, v, aoh);
    hgemm<<<dim3(DIM / BN, ROWS / BM), 256>>>(aoh, who, out, ROWS, DIM, DIM);
}

// round 8
// speedup vs baseline: 4.8014x; 1.1155x over previous
#include <cuda_runtime.h>
#include <cuda_fp16.h>
#include <cstdint>
#include <math.h>

#define DIM    1024
#define HEADS  16
#define DH     64
#define SEG    512
#define PMEM   16
#define BATCH  2
#define NSEQ   4096
#define WSEG   (NSEQ / SEG)       // 8
#define BW     (BATCH * WSEG)     // 16
#define ROWS   (BATCH * NSEQ)     // 8192
#define KV     (SEG + PMEM)       // 528
#define RMS_EPS 1.1920929e-07f

// ---------------- scratch (no cudaMalloc allowed) ----------------
__device__ __half g_xnh[(size_t)ROWS * DIM];
__device__ __half g_whq[(size_t)3 * DIM * DIM];
__device__ __half g_who[(size_t)DIM * DIM];
__device__ float  g_qkv[(size_t)ROWS * 3 * DIM];
__device__ float  g_q  [(size_t)BW * HEADS * SEG * DH];
__device__ float  g_k  [(size_t)BW * HEADS * KV  * DH];
__device__ float  g_v  [(size_t)BW * HEADS * KV  * DH];
__device__ __half g_aoh[(size_t)ROWS * DIM];

// ---------------- helpers ----------------
__device__ __forceinline__ float t32(float f) {
    unsigned r;
    asm("cvt.rna.tf32.f32 %0, %1;" : "=r"(r) : "f"(f));
    return __uint_as_float(r);
}

__device__ __forceinline__ float exp2p(float y) {
    y = fmaxf(y, -126.0f);
    float z = y + 12582912.0f;
    int   n = __float_as_int(z) - 0x4B400000;
    float f = y - (z - 12582912.0f);
    float p = 1.33336e-3f;
    p = fmaf(p, f, 9.61813e-3f);
    p = fmaf(p, f, 5.55041e-2f);
    p = fmaf(p, f, 2.40226502e-1f);
    p = fmaf(p, f, 6.93147182e-1f);
    p = fmaf(p, f, 1.0f);
    return p * __int_as_float((n + 127) << 23);
}

__device__ __forceinline__ void mma_tf32(float c[4], float a0, float a1, float a2, float a3,
                                         float b0, float b1) {
    asm volatile(
        "mma.sync.aligned.m16n8k8.row.col.f32.tf32.tf32.f32 "
        "{%0,%1,%2,%3}, {%4,%5,%6,%7}, {%8,%9}, {%0,%1,%2,%3};"
        : "+f"(c[0]), "+f"(c[1]), "+f"(c[2]), "+f"(c[3])
        : "r"(__float_as_uint(a0)), "r"(__float_as_uint(a1)),
          "r"(__float_as_uint(a2)), "r"(__float_as_uint(a3)),
          "r"(__float_as_uint(b0)), "r"(__float_as_uint(b1)));
}

__device__ __forceinline__ void mma_f16(float c[4], unsigned a0, unsigned a1, unsigned a2,
                                        unsigned a3, unsigned b0, unsigned b1) {
    asm volatile(
        "mma.sync.aligned.m16n8k16.row.col.f32.f16.f16.f32 "
        "{%0,%1,%2,%3}, {%4,%5,%6,%7}, {%8,%9}, {%0,%1,%2,%3};"
        : "+f"(c[0]), "+f"(c[1]), "+f"(c[2]), "+f"(c[3])
        : "r"(a0), "r"(a1), "r"(a2), "r"(a3), "r"(b0), "r"(b1));
}

__device__ __forceinline__ void ldsm4(unsigned r[4], unsigned addr) {
    asm volatile("ldmatrix.sync.aligned.m8n8.x4.shared.b16 {%0,%1,%2,%3}, [%4];"
                 : "=r"(r[0]), "=r"(r[1]), "=r"(r[2]), "=r"(r[3]) : "r"(addr));
}

__device__ __forceinline__ void cpasync16(unsigned dst, const void* src) {
    asm volatile("cp.async.ca.shared.global [%0], [%1], 16;" :: "r"(dst), "l"(src));
}
__device__ __forceinline__ void cpcommit() {
    asm volatile("cp.async.commit_group;");
}
template <int N>
__device__ __forceinline__ void cpwait() {
    asm volatile("cp.async.wait_group %0;" :: "n"(N));
}

// ---------------- weight fp32 -> fp16 ----------------
__global__ __launch_bounds__(256) void f2h_kernel(const float* __restrict__ s,
                                                  __half* __restrict__ d, int n4) {
    int i = blockIdx.x * 256 + threadIdx.x;
    if (i < n4) {
        float4 v = ((const float4*)s)[i];
        __half2 h0 = __floats2half2_rn(v.x, v.y);
        __half2 h1 = __floats2half2_rn(v.z, v.w);
        ((uint2*)d)[i] = make_uint2(*(unsigned*)&h0, *(unsigned*)&h1);
    }
}

// ---------------- RMSNorm (fp16 out) ----------------
__global__ __launch_bounds__(256) void rmsnorm_kernel(const float* __restrict__ seq,
                                                      const float* __restrict__ g,
                                                      __half* __restrict__ xnh) {
    int row = blockIdx.x;
    int tid = threadIdx.x;
    const float4* in = (const float4*)(seq + (size_t)row * DIM);
    float4 v = in[tid];
    float ss = v.x * v.x + v.y * v.y + v.z * v.z + v.w * v.w;
    #pragma unroll
    for (int o = 16; o; o >>= 1) ss += __shfl_xor_sync(0xFFFFFFFFu, ss, o);
    __shared__ float wsum[8];
    __shared__ float srms;
    if ((tid & 31) == 0) wsum[tid >> 5] = ss;
    __syncthreads();
    if (tid == 0) {
        float t = 0.f;
        #pragma unroll
        for (int i = 0; i < 8; i++) t += wsum[i];
        srms = rsqrtf(t * (1.0f / DIM) + RMS_EPS);
    }
    __syncthreads();
    float r = srms;
    float4 gv = ((const float4*)g)[tid];
    __half2 h0 = __floats2half2_rn(v.x * r * gv.x, v.y * r * gv.y);
    __half2 h1 = __floats2half2_rn(v.z * r * gv.z, v.w * r * gv.w);
    ((uint2*)(xnh + (size_t)row * DIM))[tid] = make_uint2(*(unsigned*)&h0, *(unsigned*)&h1);
}

// ---------------- FP16 GEMM: C[M,N] = A[M,K] * B[N,K]^T ----------------
// 128x128 CTA, KC=64, 2-stage cp.async pipeline, ldmatrix frag loads
#define BM 128
#define BN 128
#define KC 64
#define HS 72                      // halves per smem row (144B, 16B-aligned, conflict-free)
#define SSZ (BM * HS)              // halves per matrix per stage
#define GEMM_SMEM (2 * 2 * SSZ * 2)  // 73728 bytes

__global__ __launch_bounds__(256) void hgemm(const __half* __restrict__ A,
                                             const __half* __restrict__ Bm,
                                             float* __restrict__ C,
                                             int M, int Nn, int K) {
    extern __shared__ __half sh[];
    unsigned smem_base = (unsigned)__cvta_generic_to_shared(sh);

    int tid = threadIdx.x;
    int bm = blockIdx.y * BM;
    int bn = blockIdx.x * BN;

    int wid  = tid >> 5;
    int lane = tid & 31;
    int warp_m = (wid & 3) * 32;
    int warp_n = (wid >> 2) * 64;
    int grp = lane >> 2;
    int qid = lane & 3;

    float c[2][8][4];
    #pragma unroll
    for (int i = 0; i < 2; i++)
        #pragma unroll
        for (int j = 0; j < 8; j++)
            #pragma unroll
            for (int u = 0; u < 4; u++) c[i][j][u] = 0.f;

    const int NT = K / KC;

    // cp.async issue of tile kt into stage s
    auto issue = [&](int kt, int s) {
        unsigned sb = smem_base + (unsigned)(s * 2 * SSZ * 2);
        int k0 = kt * KC;
        #pragma unroll
        for (int i = 0; i < 4; i++) {
            int chunk = tid + 256 * i;         // 0..1023
            int row = chunk >> 3;              // 0..127
            int c8 = (chunk & 7) * 8;          // halves 0..56
            unsigned off = (unsigned)(row * HS + c8) * 2;
            cpasync16(sb + off, A + (size_t)(bm + row) * K + k0 + c8);
            cpasync16(sb + (unsigned)(SSZ * 2) + off, Bm + (size_t)(bn + row) * K + k0 + c8);
        }
        cpcommit();
    };

    // ldmatrix per-lane address components
    int aRow = warp_m + (lane & 15);           // + mf*16
    int aCol = (lane & 16) >> 1;               // halves 0 or 8
    int nOff = (lane & 7) | ((lane & 16) >> 1);
    int kOff = lane & 8;                       // halves 0 or 8

    issue(0, 0);

    for (int kt = 0; kt < NT; kt++) {
        if (kt + 1 < NT) {
            issue(kt + 1, (kt + 1) & 1);
            cpwait<1>();
        } else {
            cpwait<0>();
        }
        __syncthreads();

        unsigned sb = smem_base + (unsigned)((kt & 1) * 2 * SSZ * 2);
        unsigned aAddr = sb + (unsigned)(aRow * HS + aCol) * 2;
        unsigned bAddr = sb + (unsigned)(SSZ * 2) + (unsigned)((warp_n + nOff) * HS + kOff) * 2;

        #pragma unroll
        for (int ks = 0; ks < 4; ks++) {
            unsigned a0[4], a1[4];
            ldsm4(a0, aAddr + ks * 32);
            ldsm4(a1, aAddr + (unsigned)(16 * HS * 2) + ks * 32);
            unsigned bf[4][4];
            #pragma unroll
            for (int nt = 0; nt < 4; nt++)
                ldsm4(bf[nt], bAddr + (unsigned)(nt * 16 * HS * 2) + ks * 32);
            #pragma unroll
            for (int nt = 0; nt < 4; nt++) {
                mma_f16(c[0][2 * nt    ], a0[0], a0[1], a0[2], a0[3], bf[nt][0], bf[nt][1]);
                mma_f16(c[0][2 * nt + 1], a0[0], a0[1], a0[2], a0[3], bf[nt][2], bf[nt][3]);
                mma_f16(c[1][2 * nt    ], a1[0], a1[1], a1[2], a1[3], bf[nt][0], bf[nt][1]);
                mma_f16(c[1][2 * nt + 1], a1[0], a1[1], a1[2], a1[3], bf[nt][2], bf[nt][3]);
            }
        }
        __syncthreads();
    }

    #pragma unroll
    for (int mf = 0; mf < 2; mf++) {
        int row0 = bm + warp_m + mf * 16 + grp;
        #pragma unroll
        for (int nf = 0; nf < 8; nf++) {
            int col = bn + warp_n + nf * 8 + qid * 2;
            *(float2*)(C + (size_t)row0 * Nn + col)       = make_float2(c[mf][nf][0], c[mf][nf][1]);
            *(float2*)(C + (size_t)(row0 + 8) * Nn + col) = make_float2(c[mf][nf][2], c[mf][nf][3]);
        }
    }
}

// ---------------- persistent-memory prepend ----------------
__global__ __launch_bounds__(1024) void pm_fill(const float* __restrict__ pm,
                                                float* __restrict__ k,
                                                float* __restrict__ v) {
    int bwh = blockIdx.x;
    int h = bwh & 15;
    int t = threadIdx.x;
    int p = t >> 6;
    int d = t & 63;
    float kv_ = pm[((size_t)h * PMEM + p) * DH + d];
    float vv_ = pm[(size_t)HEADS * PMEM * DH + ((size_t)h * PMEM + p) * DH + d];
    k[((size_t)bwh * KV + p) * DH + d] = kv_;
    v[((size_t)bwh * KV + p) * DH + d] = vv_;
}

// ---------------- RoPE + reshape + segment scatter ----------------
__global__ __launch_bounds__(512) void rope_scatter(const float* __restrict__ qkv,
                                                    float* __restrict__ q,
                                                    float* __restrict__ k,
                                                    float* __restrict__ v) {
    int m = blockIdx.x;
    int b = m >> 12;
    int npos = m & 4095;
    int t = threadIdx.x;
    int h = t >> 5;
    int d = (t & 31) * 2;

    const float* row = qkv + (size_t)m * 3 * DIM;
    float2 qv = *(const float2*)(row + h * DH + d);
    float2 kv2 = *(const float2*)(row + DIM + h * DH + d);
    float2 vv = *(const float2*)(row + 2 * DIM + h * DH + d);

    float inv = 1.0f / powf(10000.0f, (float)d * (1.0f / 64.0f));
    float ang = (float)npos * inv;
    float sn, cs;
    sincosf(ang, &sn, &cs);
    float2 qr, kr;
    qr.x = qv.x * cs - qv.y * sn;  qr.y = qv.y * cs + qv.x * sn;
    kr.x = kv2.x * cs - kv2.y * sn; kr.y = kv2.y * cs + kv2.x * sn;

    int w = npos >> 9;
    int sidx = npos & 511;
    int bwh = (b * WSEG + w) * HEADS + h;
    *(float2*)(q + ((size_t)bwh * SEG + sidx) * DH + d) = qr;
    *(float2*)(k + ((size_t)bwh * KV + PMEM + sidx) * DH + d) = kr;
    *(float2*)(v + ((size_t)bwh * KV + PMEM + sidx) * DH + d) = vv;
}

// ---------------- tensor-core flash attention (half out) ----------------
#define KSTR 68

__global__ __launch_bounds__(256) void attn_tc(const float* __restrict__ Q,
                                               const float* __restrict__ K,
                                               const float* __restrict__ V,
                                               __half* __restrict__ AO) {
    __shared__ float sK [64][KSTR];
    __shared__ float sVt[64][KSTR];

    const int tid  = threadIdx.x;
    const int wid  = tid >> 5;
    const int lane = tid & 31;
    const int grp  = lane >> 2;
    const int qid  = lane & 3;
    const int bwh  = blockIdx.y;
    const int q0   = blockIdx.x * 128;
    const int wq0  = q0 + wid * 16;

    const float* Qb = Q + (size_t)bwh * SEG * DH;
    const float* Kb = K + (size_t)bwh * KV * DH;
    const float* Vb = V + (size_t)bwh * KV * DH;

    const int r  = tid >> 2;
    const int c4 = tid & 3;

    const float QSC = 0.125f * 1.4426950408889634f;
    float aq[8][4];
    #pragma unroll
    for (int pass = 0; pass < 2; pass++) {
        const float* qg = Qb + (size_t)(q0 + pass * 64 + r) * DH + c4 * 16;
        #pragma unroll
        for (int u = 0; u < 4; u++) {
            float4 x = *(const float4*)(qg + u * 4);
            x.x = t32(x.x * QSC); x.y = t32(x.y * QSC);
            x.z = t32(x.z * QSC); x.w = t32(x.w * QSC);
            *(float4*)&sK[r][c4 * 16 + u * 4] = x;
        }
        __syncthreads();
        if ((wid >> 2) == pass) {
            int lr = (wid & 3) * 16 + grp;
            #pragma unroll
            for (int ks = 0; ks < 8; ks++) {
                aq[ks][0] = sK[lr    ][ks * 8 + qid    ];
                aq[ks][1] = sK[lr + 8][ks * 8 + qid    ];
                aq[ks][2] = sK[lr    ][ks * 8 + qid + 4];
                aq[ks][3] = sK[lr + 8][ks * 8 + qid + 4];
            }
        }
        __syncthreads();
    }

    float o[8][4];
    #pragma unroll
    for (int nf = 0; nf < 8; nf++)
        #pragma unroll
        for (int u = 0; u < 4; u++) o[nf][u] = 0.f;
    float m0 = -1e30f, m1 = -1e30f, l0 = 0.f, l1 = 0.f;

    int jmax = q0 + 128 + PMEM;
    if (jmax > KV) jmax = KV;
    int ntiles = (jmax + 63) >> 6;

    for (int t = 0; t < ntiles; t++) {
        int jj0 = t << 6;
        {
            int jj = jj0 + r;
            if (jj < KV) {
                const float* kg = Kb + (size_t)jj * DH + c4 * 16;
                const float* vg = Vb + (size_t)jj * DH + c4 * 16;
                #pragma unroll
                for (int u = 0; u < 4; u++) {
                    float4 kx = *(const float4*)(kg + u * 4);
                    kx.x = t32(kx.x); kx.y = t32(kx.y); kx.z = t32(kx.z); kx.w = t32(kx.w);
                    *(float4*)&sK[r][c4 * 16 + u * 4] = kx;
                    float4 vx = *(const float4*)(vg + u * 4);
                    int db = c4 * 16 + u * 4;
                    sVt[db + 0][r] = t32(vx.x);
                    sVt[db + 1][r] = t32(vx.y);
                    sVt[db + 2][r] = t32(vx.z);
                    sVt[db + 3][r] = t32(vx.w);
                }
            } else {
                #pragma unroll
                for (int u = 0; u < 4; u++) {
                    *(float4*)&sK[r][c4 * 16 + u * 4] = make_float4(0.f, 0.f, 0.f, 0.f);
                    int db = c4 * 16 + u * 4;
                    sVt[db + 0][r] = 0.f; sVt[db + 1][r] = 0.f;
                    sVt[db + 2][r] = 0.f; sVt[db + 3][r] = 0.f;
                }
            }
        }
        __syncthreads();

        if (jj0 <= wq0 + 15 + PMEM) {
            float c[8][4];
            #pragma unroll
            for (int nf = 0; nf < 8; nf++)
                #pragma unroll
                for (int u = 0; u < 4; u++) c[nf][u] = 0.f;

            #pragma unroll
            for (int ks = 0; ks < 8; ks++) {
                #pragma unroll
                for (int nf = 0; nf < 8; nf++) {
                    float b0 = sK[nf * 8 + grp][ks * 8 + qid    ];
                    float b1 = sK[nf * 8 + grp][ks * 8 + qid + 4];
                    mma_tf32(c[nf], aq[ks][0], aq[ks][1], aq[ks][2], aq[ks][3], b0, b1);
                }
            }

            if (jj0 + 63 > wq0 + PMEM) {
                int r0 = wq0 + grp, r1 = r0 + 8;
                #pragma unroll
                for (int nf = 0; nf < 8; nf++) {
                    int j0 = jj0 + nf * 8 + 2 * qid;
                    if (j0     - PMEM > r0) c[nf][0] = -1e30f;
                    if (j0 + 1 - PMEM > r0) c[nf][1] = -1e30f;
                    if (j0     - PMEM > r1) c[nf][2] = -1e30f;
                    if (j0 + 1 - PMEM > r1) c[nf][3] = -1e30f;
                }
            }

            float mt0 = -1e30f, mt1 = -1e30f;
            #pragma unroll
            for (int nf = 0; nf < 8; nf++) {
                mt0 = fmaxf(mt0, fmaxf(c[nf][0], c[nf][1]));
                mt1 = fmaxf(mt1, fmaxf(c[nf][2], c[nf][3]));
            }
            mt0 = fmaxf(mt0, __shfl_xor_sync(0xFFFFFFFFu, mt0, 1));
            mt0 = fmaxf(mt0, __shfl_xor_sync(0xFFFFFFFFu, mt0, 2));
            mt1 = fmaxf(mt1, __shfl_xor_sync(0xFFFFFFFFu, mt1, 1));
            mt1 = fmaxf(mt1, __shfl_xor_sync(0xFFFFFFFFu, mt1, 2));

            float nm0 = fmaxf(m0, mt0), nm1 = fmaxf(m1, mt1);
            float f0 = exp2p(m0 - nm0), f1 = exp2p(m1 - nm1);
            m0 = nm0; m1 = nm1;
            l0 *= f0; l1 *= f1;
            #pragma unroll
            for (int nf = 0; nf < 8; nf++) {
                o[nf][0] *= f0; o[nf][1] *= f0;
                o[nf][2] *= f1; o[nf][3] *= f1;
            }

            float s0 = 0.f, s1 = 0.f;
            #pragma unroll
            for (int nf = 0; nf < 8; nf++) {
                float p00 = t32(exp2p(c[nf][0] - m0));
                float p01 = t32(exp2p(c[nf][1] - m0));
                float p10 = t32(exp2p(c[nf][2] - m1));
                float p11 = t32(exp2p(c[nf][3] - m1));
                c[nf][0] = p00; c[nf][1] = p01; c[nf][2] = p10; c[nf][3] = p11;
                s0 += p00 + p01; s1 += p10 + p11;
            }
            s0 += __shfl_xor_sync(0xFFFFFFFFu, s0, 1);
            s0 += __shfl_xor_sync(0xFFFFFFFFu, s0, 2);
            s1 += __shfl_xor_sync(0xFFFFFFFFu, s1, 1);
            s1 += __shfl_xor_sync(0xFFFFFFFFu, s1, 2);
            l0 += s0; l1 += s1;

            int qbase = lane & ~3;
            int qs0 = qbase | (qid >> 1);
            int qs2 = qbase | (2 + (qid >> 1));
            bool hi = (qid & 1);
            #pragma unroll
            for (int kk = 0; kk < 8; kk++) {
                float x0 = __shfl_sync(0xFFFFFFFFu, c[kk][0], qs0);
                float x1 = __shfl_sync(0xFFFFFFFFu, c[kk][1], qs0);
                float a0 = hi ? x1 : x0;
                float z0 = __shfl_sync(0xFFFFFFFFu, c[kk][2], qs0);
                float z1 = __shfl_sync(0xFFFFFFFFu, c[kk][3], qs0);
                float a1 = hi ? z1 : z0;
                float x2 = __shfl_sync(0xFFFFFFFFu, c[kk][0], qs2);
                float x3 = __shfl_sync(0xFFFFFFFFu, c[kk][1], qs2);
                float a2 = hi ? x3 : x2;
                float z2 = __shfl_sync(0xFFFFFFFFu, c[kk][2], qs2);
                float z3 = __shfl_sync(0xFFFFFFFFu, c[kk][3], qs2);
                float a3 = hi ? z3 : z2;
                #pragma unroll
                for (int nf = 0; nf < 8; nf++) {
                    float b0 = sVt[nf * 8 + grp][kk * 8 + qid    ];
                    float b1 = sVt[nf * 8 + grp][kk * 8 + qid + 4];
                    mma_tf32(o[nf], a0, a1, a2, a3, b0, b1);
                }
            }
        }
        __syncthreads();
    }

    float inv0 = 1.0f / l0, inv1 = 1.0f / l1;
    int bw = bwh >> 4, h = bwh & 15;
    int r0 = wq0 + grp, r1 = r0 + 8;
    __half* out0 = AO + (size_t)(bw * SEG + r0) * DIM + h * DH;
    __half* out1 = AO + (size_t)(bw * SEG + r1) * DIM + h * DH;
    #pragma unroll
    for (int nf = 0; nf < 8; nf++) {
        int col = nf * 8 + 2 * qid;
        __half2 h0 = __floats2half2_rn(o[nf][0] * inv0, o[nf][1] * inv0);
        __half2 h1 = __floats2half2_rn(o[nf][2] * inv1, o[nf][3] * inv1);
        *(unsigned*)(out0 + col) = *(unsigned*)&h0;
        *(unsigned*)(out1 + col) = *(unsigned*)&h1;
    }
}

// ---------------- launch ----------------
extern "C" void kernel_launch(void* const* d_in, const int* in_sizes, int n_in,
                              void* d_out, int out_size) {
    const float* seq   = (const float*)d_in[0];
    const float* g     = (const float*)d_in[1];
    const float* w_qkv = (const float*)d_in[2];
    const float* w_out = (const float*)d_in[3];
    const float* pm    = (const float*)d_in[4];
    float* out = (float*)d_out;

    __half *xnh, *whq, *who, *aoh;
    float *qkv, *q, *k, *v;
    cudaGetSymbolAddress((void**)&xnh, g_xnh);
    cudaGetSymbolAddress((void**)&whq, g_whq);
    cudaGetSymbolAddress((void**)&who, g_who);
    cudaGetSymbolAddress((void**)&qkv, g_qkv);
    cudaGetSymbolAddress((void**)&q,   g_q);
    cudaGetSymbolAddress((void**)&k,   g_k);
    cudaGetSymbolAddress((void**)&v,   g_v);
    cudaGetSymbolAddress((void**)&aoh, g_aoh);

    static int smem_set = 0;
    if (!smem_set) {
        cudaFuncSetAttribute(hgemm, cudaFuncAttributeMaxDynamicSharedMemorySize, GEMM_SMEM);
        smem_set = 1;
    }

    f2h_kernel<<<(3 * DIM * DIM / 4 + 255) / 256, 256>>>(w_qkv, whq, 3 * DIM * DIM / 4);
    f2h_kernel<<<(DIM * DIM / 4 + 255) / 256, 256>>>(w_out, who, DIM * DIM / 4);
    rmsnorm_kernel<<<ROWS, 256>>>(seq, g, xnh);
    hgemm<<<dim3(3 * DIM / BN, ROWS / BM), 256, GEMM_SMEM>>>(xnh, whq, qkv, ROWS, 3 * DIM, DIM);
    pm_fill<<<BW * HEADS, 1024>>>(pm, k, v);
    rope_scatter<<<ROWS, 512>>>(qkv, q, k, v);
    attn_tc<<<dim3(4, BW * HEADS), 256>>>(q, k, v, aoh);
    hgemm<<<dim3(DIM / BN, ROWS / BM), 256, GEMM_SMEM>>>(aoh, who, out, ROWS, DIM, DIM);
}

// round 9
// speedup vs baseline: 6.0043x; 1.2505x over previous
#include <cuda_runtime.h>
#include <cuda_fp16.h>
#include <cstdint>
#include <math.h>

#define DIM    1024
#define HEADS  16
#define DH     64
#define SEG    512
#define PMEM   16
#define BATCH  2
#define NSEQ   4096
#define WSEG   (NSEQ / SEG)       // 8
#define BW     (BATCH * WSEG)     // 16
#define ROWS   (BATCH * NSEQ)     // 8192
#define KV     (SEG + PMEM)       // 528
#define RMS_EPS 1.1920929e-07f

// ---------------- scratch (no cudaMalloc allowed) ----------------
__device__ __half g_xnh[(size_t)ROWS * DIM];
__device__ __half g_whq[(size_t)3 * DIM * DIM];
__device__ __half g_who[(size_t)DIM * DIM];
__device__ float  g_qkv[(size_t)ROWS * 3 * DIM];
__device__ __half g_q  [(size_t)BW * HEADS * SEG * DH];
__device__ __half g_k  [(size_t)BW * HEADS * KV  * DH];
__device__ __half g_v  [(size_t)BW * HEADS * KV  * DH];
__device__ __half g_aoh[(size_t)ROWS * DIM];

// ---------------- helpers ----------------
__device__ __forceinline__ float exp2p(float y) {
    y = fmaxf(y, -126.0f);
    float z = y + 12582912.0f;
    int   n = __float_as_int(z) - 0x4B400000;
    float f = y - (z - 12582912.0f);
    float p = 1.33336e-3f;
    p = fmaf(p, f, 9.61813e-3f);
    p = fmaf(p, f, 5.55041e-2f);
    p = fmaf(p, f, 2.40226502e-1f);
    p = fmaf(p, f, 6.93147182e-1f);
    p = fmaf(p, f, 1.0f);
    return p * __int_as_float((n + 127) << 23);
}

__device__ __forceinline__ void mma_f16(float c[4], unsigned a0, unsigned a1, unsigned a2,
                                        unsigned a3, unsigned b0, unsigned b1) {
    asm volatile(
        "mma.sync.aligned.m16n8k16.row.col.f32.f16.f16.f32 "
        "{%0,%1,%2,%3}, {%4,%5,%6,%7}, {%8,%9}, {%0,%1,%2,%3};"
        : "+f"(c[0]), "+f"(c[1]), "+f"(c[2]), "+f"(c[3])
        : "r"(a0), "r"(a1), "r"(a2), "r"(a3), "r"(b0), "r"(b1));
}

__device__ __forceinline__ void ldsm4(unsigned r[4], unsigned addr) {
    asm volatile("ldmatrix.sync.aligned.m8n8.x4.shared.b16 {%0,%1,%2,%3}, [%4];"
                 : "=r"(r[0]), "=r"(r[1]), "=r"(r[2]), "=r"(r[3]) : "r"(addr));
}

__device__ __forceinline__ void ldsm4t(unsigned r[4], unsigned addr) {
    asm volatile("ldmatrix.sync.aligned.m8n8.x4.trans.shared.b16 {%0,%1,%2,%3}, [%4];"
                 : "=r"(r[0]), "=r"(r[1]), "=r"(r[2]), "=r"(r[3]) : "r"(addr));
}

__device__ __forceinline__ unsigned packh2(float lo, float hi) {
    __half2 h = __floats2half2_rn(lo, hi);
    return *(unsigned*)&h;
}

__device__ __forceinline__ void cpasync16(unsigned dst, const void* src) {
    asm volatile("cp.async.ca.shared.global [%0], [%1], 16;" :: "r"(dst), "l"(src));
}
__device__ __forceinline__ void cpcommit() {
    asm volatile("cp.async.commit_group;");
}
template <int N>
__device__ __forceinline__ void cpwait() {
    asm volatile("cp.async.wait_group %0;" :: "n"(N));
}

// ---------------- weight fp32 -> fp16 ----------------
__global__ __launch_bounds__(256) void f2h_kernel(const float* __restrict__ s,
                                                  __half* __restrict__ d, int n4) {
    int i = blockIdx.x * 256 + threadIdx.x;
    if (i < n4) {
        float4 v = ((const float4*)s)[i];
        __half2 h0 = __floats2half2_rn(v.x, v.y);
        __half2 h1 = __floats2half2_rn(v.z, v.w);
        ((uint2*)d)[i] = make_uint2(*(unsigned*)&h0, *(unsigned*)&h1);
    }
}

// ---------------- RMSNorm (fp16 out) ----------------
__global__ __launch_bounds__(256) void rmsnorm_kernel(const float* __restrict__ seq,
                                                      const float* __restrict__ g,
                                                      __half* __restrict__ xnh) {
    int row = blockIdx.x;
    int tid = threadIdx.x;
    const float4* in = (const float4*)(seq + (size_t)row * DIM);
    float4 v = in[tid];
    float ss = v.x * v.x + v.y * v.y + v.z * v.z + v.w * v.w;
    #pragma unroll
    for (int o = 16; o; o >>= 1) ss += __shfl_xor_sync(0xFFFFFFFFu, ss, o);
    __shared__ float wsum[8];
    __shared__ float srms;
    if ((tid & 31) == 0) wsum[tid >> 5] = ss;
    __syncthreads();
    if (tid == 0) {
        float t = 0.f;
        #pragma unroll
        for (int i = 0; i < 8; i++) t += wsum[i];
        srms = rsqrtf(t * (1.0f / DIM) + RMS_EPS);
    }
    __syncthreads();
    float r = srms;
    float4 gv = ((const float4*)g)[tid];
    __half2 h0 = __floats2half2_rn(v.x * r * gv.x, v.y * r * gv.y);
    __half2 h1 = __floats2half2_rn(v.z * r * gv.z, v.w * r * gv.w);
    ((uint2*)(xnh + (size_t)row * DIM))[tid] = make_uint2(*(unsigned*)&h0, *(unsigned*)&h1);
}

// ---------------- FP16 GEMM: C[M,N] = A[M,K] * B[N,K]^T ----------------
#define BM 128
#define BN 128
#define KC 64
#define HS 72
#define SSZ (BM * HS)
#define GEMM_SMEM (2 * 2 * SSZ * 2)

__global__ __launch_bounds__(256) void hgemm(const __half* __restrict__ A,
                                             const __half* __restrict__ Bm,
                                             float* __restrict__ C,
                                             int M, int Nn, int K) {
    extern __shared__ __half sh[];
    unsigned smem_base = (unsigned)__cvta_generic_to_shared(sh);

    int tid = threadIdx.x;
    int bm = blockIdx.y * BM;
    int bn = blockIdx.x * BN;

    int wid  = tid >> 5;
    int lane = tid & 31;
    int warp_m = (wid & 3) * 32;
    int warp_n = (wid >> 2) * 64;
    int grp = lane >> 2;
    int qid = lane & 3;

    float c[2][8][4];
    #pragma unroll
    for (int i = 0; i < 2; i++)
        #pragma unroll
        for (int j = 0; j < 8; j++)
            #pragma unroll
            for (int u = 0; u < 4; u++) c[i][j][u] = 0.f;

    const int NT = K / KC;

    auto issue = [&](int kt, int s) {
        unsigned sb = smem_base + (unsigned)(s * 2 * SSZ * 2);
        int k0 = kt * KC;
        #pragma unroll
        for (int i = 0; i < 4; i++) {
            int chunk = tid + 256 * i;
            int row = chunk >> 3;
            int c8 = (chunk & 7) * 8;
            unsigned off = (unsigned)(row * HS + c8) * 2;
            cpasync16(sb + off, A + (size_t)(bm + row) * K + k0 + c8);
            cpasync16(sb + (unsigned)(SSZ * 2) + off, Bm + (size_t)(bn + row) * K + k0 + c8);
        }
        cpcommit();
    };

    int aRow = warp_m + (lane & 15);
    int aCol = (lane & 16) >> 1;
    int nOff = (lane & 7) | ((lane & 16) >> 1);
    int kOff = lane & 8;

    issue(0, 0);

    for (int kt = 0; kt < NT; kt++) {
        if (kt + 1 < NT) {
            issue(kt + 1, (kt + 1) & 1);
            cpwait<1>();
        } else {
            cpwait<0>();
        }
        __syncthreads();

        unsigned sb = smem_base + (unsigned)((kt & 1) * 2 * SSZ * 2);
        unsigned aAddr = sb + (unsigned)(aRow * HS + aCol) * 2;
        unsigned bAddr = sb + (unsigned)(SSZ * 2) + (unsigned)((warp_n + nOff) * HS + kOff) * 2;

        #pragma unroll
        for (int ks = 0; ks < 4; ks++) {
            unsigned a0[4], a1[4];
            ldsm4(a0, aAddr + ks * 32);
            ldsm4(a1, aAddr + (unsigned)(16 * HS * 2) + ks * 32);
            unsigned bf[4][4];
            #pragma unroll
            for (int nt = 0; nt < 4; nt++)
                ldsm4(bf[nt], bAddr + (unsigned)(nt * 16 * HS * 2) + ks * 32);
            #pragma unroll
            for (int nt = 0; nt < 4; nt++) {
                mma_f16(c[0][2 * nt    ], a0[0], a0[1], a0[2], a0[3], bf[nt][0], bf[nt][1]);
                mma_f16(c[0][2 * nt + 1], a0[0], a0[1], a0[2], a0[3], bf[nt][2], bf[nt][3]);
                mma_f16(c[1][2 * nt    ], a1[0], a1[1], a1[2], a1[3], bf[nt][0], bf[nt][1]);
                mma_f16(c[1][2 * nt + 1], a1[0], a1[1], a1[2], a1[3], bf[nt][2], bf[nt][3]);
            }
        }
        __syncthreads();
    }

    #pragma unroll
    for (int mf = 0; mf < 2; mf++) {
        int row0 = bm + warp_m + mf * 16 + grp;
        #pragma unroll
        for (int nf = 0; nf < 8; nf++) {
            int col = bn + warp_n + nf * 8 + qid * 2;
            *(float2*)(C + (size_t)row0 * Nn + col)       = make_float2(c[mf][nf][0], c[mf][nf][1]);
            *(float2*)(C + (size_t)(row0 + 8) * Nn + col) = make_float2(c[mf][nf][2], c[mf][nf][3]);
        }
    }
}

// ---------------- persistent-memory prepend (half) ----------------
__global__ __launch_bounds__(1024) void pm_fill(const float* __restrict__ pm,
                                                __half* __restrict__ k,
                                                __half* __restrict__ v) {
    int bwh = blockIdx.x;
    int h = bwh & 15;
    int t = threadIdx.x;
    int p = t >> 6;
    int d = t & 63;
    float kv_ = pm[((size_t)h * PMEM + p) * DH + d];
    float vv_ = pm[(size_t)HEADS * PMEM * DH + ((size_t)h * PMEM + p) * DH + d];
    k[((size_t)bwh * KV + p) * DH + d] = __float2half(kv_);
    v[((size_t)bwh * KV + p) * DH + d] = __float2half(vv_);
}

// ---------------- RoPE + reshape + segment scatter (half out, Q pre-scaled) --------
#define QSC (0.125f * 1.4426950408889634f)

__global__ __launch_bounds__(512) void rope_scatter(const float* __restrict__ qkv,
                                                    __half* __restrict__ q,
                                                    __half* __restrict__ k,
                                                    __half* __restrict__ v) {
    int m = blockIdx.x;
    int b = m >> 12;
    int npos = m & 4095;
    int t = threadIdx.x;
    int h = t >> 5;
    int d = (t & 31) * 2;

    const float* row = qkv + (size_t)m * 3 * DIM;
    float2 qv = *(const float2*)(row + h * DH + d);
    float2 kv2 = *(const float2*)(row + DIM + h * DH + d);
    float2 vv = *(const float2*)(row + 2 * DIM + h * DH + d);

    float inv = 1.0f / powf(10000.0f, (float)d * (1.0f / 64.0f));
    float ang = (float)npos * inv;
    float sn, cs;
    sincosf(ang, &sn, &cs);
    float2 qr, kr;
    qr.x = qv.x * cs - qv.y * sn;  qr.y = qv.y * cs + qv.x * sn;
    kr.x = kv2.x * cs - kv2.y * sn; kr.y = kv2.y * cs + kv2.x * sn;

    int w = npos >> 9;
    int sidx = npos & 511;
    int bwh = (b * WSEG + w) * HEADS + h;
    *(unsigned*)(q + ((size_t)bwh * SEG + sidx) * DH + d) = packh2(qr.x * QSC, qr.y * QSC);
    *(unsigned*)(k + ((size_t)bwh * KV + PMEM + sidx) * DH + d) = packh2(kr.x, kr.y);
    *(unsigned*)(v + ((size_t)bwh * KV + PMEM + sidx) * DH + d) = packh2(vv.x, vv.y);
}

// ---------------- fp16 tensor-core flash attention ----------------
#define SH2 72   // smem half stride

__global__ __launch_bounds__(256) void attn_tc(const __half* __restrict__ Q,
                                               const __half* __restrict__ K,
                                               const __half* __restrict__ V,
                                               __half* __restrict__ AO) {
    __shared__ __half sQ[128][SH2];
    __shared__ __half sK[64][SH2];
    __shared__ __half sV[64][SH2];

    const int tid  = threadIdx.x;
    const int wid  = tid >> 5;
    const int lane = tid & 31;
    const int grp  = lane >> 2;
    const int qid  = lane & 3;
    const int bwh  = blockIdx.y;
    const int q0   = blockIdx.x * 128;
    const int wq0  = q0 + wid * 16;

    const __half* Qb = Q + (size_t)bwh * SEG * DH;
    const __half* Kb = K + (size_t)bwh * KV * DH;
    const __half* Vb = V + (size_t)bwh * KV * DH;

    unsigned sQb = (unsigned)__cvta_generic_to_shared(&sQ[0][0]);
    unsigned sKb = (unsigned)__cvta_generic_to_shared(&sK[0][0]);
    unsigned sVb = (unsigned)__cvta_generic_to_shared(&sV[0][0]);

    // ---- stage Q tile, load A-fragments once ----
    #pragma unroll
    for (int i = 0; i < 4; i++) {
        int chunk = tid + 256 * i;        // 0..1023
        int row = chunk >> 3;             // 0..127
        int off = (chunk & 7) * 8;        // halves
        *(uint4*)&sQ[row][off] = *(const uint4*)(Qb + (size_t)(q0 + row) * DH + off);
    }
    __syncthreads();

    unsigned aq[4][4];
    {
        int aRow = wid * 16 + (lane & 15);
        int aCol = (lane & 16) >> 1;
        #pragma unroll
        for (int kc = 0; kc < 4; kc++)
            ldsm4(aq[kc], sQb + (unsigned)(aRow * SH2 + kc * 16 + aCol) * 2);
    }

    float o[8][4];
    #pragma unroll
    for (int nf = 0; nf < 8; nf++)
        #pragma unroll
        for (int u = 0; u < 4; u++) o[nf][u] = 0.f;
    float m0 = -1e30f, m1 = -1e30f, l0 = 0.f, l1 = 0.f;

    int jmax = q0 + 128 + PMEM;
    if (jmax > KV) jmax = KV;
    int ntiles = (jmax + 63) >> 6;

    const int r  = tid >> 2;     // staging key row
    const int c4 = tid & 3;      // 16-half chunk

    const int fRow = lane & 15;           // ldmatrix row component
    const int fCol = (lane & 16) >> 1;    // ldmatrix col-octet (halves)
    const int nRow = (lane & 7) | ((lane & 16) >> 1);
    const int kOff = lane & 8;

    for (int t = 0; t < ntiles; t++) {
        int jj0 = t << 6;
        {
            int jj = jj0 + r;
            if (jj < KV) {
                const uint4* kg = (const uint4*)(Kb + (size_t)jj * DH + c4 * 16);
                const uint4* vg = (const uint4*)(Vb + (size_t)jj * DH + c4 * 16);
                *(uint4*)&sK[r][c4 * 16]     = kg[0];
                *(uint4*)&sK[r][c4 * 16 + 8] = kg[1];
                *(uint4*)&sV[r][c4 * 16]     = vg[0];
                *(uint4*)&sV[r][c4 * 16 + 8] = vg[1];
            } else {
                uint4 z = make_uint4(0, 0, 0, 0);
                *(uint4*)&sK[r][c4 * 16]     = z;
                *(uint4*)&sK[r][c4 * 16 + 8] = z;
                *(uint4*)&sV[r][c4 * 16]     = z;
                *(uint4*)&sV[r][c4 * 16 + 8] = z;
            }
        }
        __syncthreads();

        if (jj0 <= wq0 + 15 + PMEM) {
            // ---- S = Q K^T (log2 domain, fp16 mma) ----
            float c[8][4];
            #pragma unroll
            for (int nf = 0; nf < 8; nf++)
                #pragma unroll
                for (int u = 0; u < 4; u++) c[nf][u] = 0.f;

            #pragma unroll
            for (int kc = 0; kc < 4; kc++) {
                #pragma unroll
                for (int ng = 0; ng < 4; ng++) {
                    unsigned b[4];
                    ldsm4(b, sKb + (unsigned)((ng * 16 + nRow) * SH2 + kc * 16 + kOff) * 2);
                    mma_f16(c[2 * ng    ], aq[kc][0], aq[kc][1], aq[kc][2], aq[kc][3], b[0], b[1]);
                    mma_f16(c[2 * ng + 1], aq[kc][0], aq[kc][1], aq[kc][2], aq[kc][3], b[2], b[3]);
                }
            }

            // ---- causal mask ----
            if (jj0 + 63 > wq0 + PMEM) {
                int r0 = wq0 + grp, r1 = r0 + 8;
                #pragma unroll
                for (int nf = 0; nf < 8; nf++) {
                    int j0 = jj0 + nf * 8 + 2 * qid;
                    if (j0     - PMEM > r0) c[nf][0] = -1e30f;
                    if (j0 + 1 - PMEM > r0) c[nf][1] = -1e30f;
                    if (j0     - PMEM > r1) c[nf][2] = -1e30f;
                    if (j0 + 1 - PMEM > r1) c[nf][3] = -1e30f;
                }
            }

            // ---- online softmax (base-2) ----
            float mt0 = -1e30f, mt1 = -1e30f;
            #pragma unroll
            for (int nf = 0; nf < 8; nf++) {
                mt0 = fmaxf(mt0, fmaxf(c[nf][0], c[nf][1]));
                mt1 = fmaxf(mt1, fmaxf(c[nf][2], c[nf][3]));
            }
            mt0 = fmaxf(mt0, __shfl_xor_sync(0xFFFFFFFFu, mt0, 1));
            mt0 = fmaxf(mt0, __shfl_xor_sync(0xFFFFFFFFu, mt0, 2));
            mt1 = fmaxf(mt1, __shfl_xor_sync(0xFFFFFFFFu, mt1, 1));
            mt1 = fmaxf(mt1, __shfl_xor_sync(0xFFFFFFFFu, mt1, 2));

            float nm0 = fmaxf(m0, mt0), nm1 = fmaxf(m1, mt1);
            float f0 = exp2p(m0 - nm0), f1 = exp2p(m1 - nm1);
            m0 = nm0; m1 = nm1;
            l0 *= f0; l1 *= f1;
            #pragma unroll
            for (int nf = 0; nf < 8; nf++) {
                o[nf][0] *= f0; o[nf][1] *= f0;
                o[nf][2] *= f1; o[nf][3] *= f1;
            }

            float s0 = 0.f, s1 = 0.f;
            #pragma unroll
            for (int nf = 0; nf < 8; nf++) {
                float p00 = exp2p(c[nf][0] - m0);
                float p01 = exp2p(c[nf][1] - m0);
                float p10 = exp2p(c[nf][2] - m1);
                float p11 = exp2p(c[nf][3] - m1);
                c[nf][0] = p00; c[nf][1] = p01; c[nf][2] = p10; c[nf][3] = p11;
                s0 += p00 + p01; s1 += p10 + p11;
            }
            s0 += __shfl_xor_sync(0xFFFFFFFFu, s0, 1);
            s0 += __shfl_xor_sync(0xFFFFFFFFu, s0, 2);
            s1 += __shfl_xor_sync(0xFFFFFFFFu, s1, 1);
            s1 += __shfl_xor_sync(0xFFFFFFFFu, s1, 2);
            l0 += s0; l1 += s1;

            // ---- pack P into fp16 A-fragments (no shuffles) ----
            unsigned ph[4][4];
            #pragma unroll
            for (int kc = 0; kc < 4; kc++) {
                ph[kc][0] = packh2(c[2 * kc    ][0], c[2 * kc    ][1]);
                ph[kc][1] = packh2(c[2 * kc    ][2], c[2 * kc    ][3]);
                ph[kc][2] = packh2(c[2 * kc + 1][0], c[2 * kc + 1][1]);
                ph[kc][3] = packh2(c[2 * kc + 1][2], c[2 * kc + 1][3]);
            }

            // ---- O += P V (V via ldmatrix.trans) ----
            #pragma unroll
            for (int kc = 0; kc < 4; kc++) {
                #pragma unroll
                for (int dg = 0; dg < 4; dg++) {
                    unsigned b[4];
                    ldsm4t(b, sVb + (unsigned)((kc * 16 + fRow) * SH2 + dg * 16 + fCol) * 2);
                    mma_f16(o[2 * dg    ], ph[kc][0], ph[kc][1], ph[kc][2], ph[kc][3], b[0], b[1]);
                    mma_f16(o[2 * dg + 1], ph[kc][0], ph[kc][1], ph[kc][2], ph[kc][3], b[2], b[3]);
                }
            }
        }
        __syncthreads();
    }

    // ---- epilogue ----
    float inv0 = 1.0f / l0, inv1 = 1.0f / l1;
    int bw = bwh >> 4, h = bwh & 15;
    int r0 = wq0 + grp, r1 = r0 + 8;
    __half* out0 = AO + (size_t)(bw * SEG + r0) * DIM + h * DH;
    __half* out1 = AO + (size_t)(bw * SEG + r1) * DIM + h * DH;
    #pragma unroll
    for (int nf = 0; nf < 8; nf++) {
        int col = nf * 8 + 2 * qid;
        *(unsigned*)(out0 + col) = packh2(o[nf][0] * inv0, o[nf][1] * inv0);
        *(unsigned*)(out1 + col) = packh2(o[nf][2] * inv1, o[nf][3] * inv1);
    }
}

// ---------------- launch ----------------
extern "C" void kernel_launch(void* const* d_in, const int* in_sizes, int n_in,
                              void* d_out, int out_size) {
    const float* seq   = (const float*)d_in[0];
    const float* g     = (const float*)d_in[1];
    const float* w_qkv = (const float*)d_in[2];
    const float* w_out = (const float*)d_in[3];
    const float* pm    = (const float*)d_in[4];
    float* out = (float*)d_out;

    __half *xnh, *whq, *who, *aoh, *q, *k, *v;
    float *qkv;
    cudaGetSymbolAddress((void**)&xnh, g_xnh);
    cudaGetSymbolAddress((void**)&whq, g_whq);
    cudaGetSymbolAddress((void**)&who, g_who);
    cudaGetSymbolAddress((void**)&qkv, g_qkv);
    cudaGetSymbolAddress((void**)&q,   g_q);
    cudaGetSymbolAddress((void**)&k,   g_k);
    cudaGetSymbolAddress((void**)&v,   g_v);
    cudaGetSymbolAddress((void**)&aoh, g_aoh);

    static int smem_set = 0;
    if (!smem_set) {
        cudaFuncSetAttribute(hgemm, cudaFuncAttributeMaxDynamicSharedMemorySize, GEMM_SMEM);
        smem_set = 1;
    }

    f2h_kernel<<<(3 * DIM * DIM / 4 + 255) / 256, 256>>>(w_qkv, whq, 3 * DIM * DIM / 4);
    f2h_kernel<<<(DIM * DIM / 4 + 255) / 256, 256>>>(w_out, who, DIM * DIM / 4);
    rmsnorm_kernel<<<ROWS, 256>>>(seq, g, xnh);
    hgemm<<<dim3(3 * DIM / BN, ROWS / BM), 256, GEMM_SMEM>>>(xnh, whq, qkv, ROWS, 3 * DIM, DIM);
    pm_fill<<<BW * HEADS, 1024>>>(pm, k, v);
    rope_scatter<<<ROWS, 512>>>(qkv, q, k, v);
    attn_tc<<<dim3(4, BW * HEADS), 256>>>(q, k, v, aoh);
    hgemm<<<dim3(DIM / BN, ROWS / BM), 256, GEMM_SMEM>>>(aoh, who, out, ROWS, DIM, DIM);
}

// round 11
// speedup vs baseline: 6.4542x; 1.0749x over previous
#include <cuda_runtime.h>
#include <cuda_fp16.h>
#include <cstdint>
#include <math.h>

#define DIM    1024
#define HEADS  16
#define DH     64
#define SEG    512
#define PMEM   16
#define BATCH  2
#define NSEQ   4096
#define WSEG   (NSEQ / SEG)       // 8
#define BW     (BATCH * WSEG)     // 16
#define ROWS   (BATCH * NSEQ)     // 8192
#define KV     (SEG + PMEM)       // 528
#define RMS_EPS 1.1920929e-07f

// ---------------- scratch (no cudaMalloc allowed) ----------------
__device__ __half g_xnh[(size_t)ROWS * DIM];
__device__ __half g_whq[(size_t)3 * DIM * DIM];
__device__ __half g_who[(size_t)DIM * DIM];
__device__ __half g_qkv[(size_t)ROWS * 3 * DIM];   // half now
__device__ __half g_q  [(size_t)BW * HEADS * SEG * DH];
__device__ __half g_k  [(size_t)BW * HEADS * KV  * DH];
__device__ __half g_v  [(size_t)BW * HEADS * KV  * DH];
__device__ __half g_aoh[(size_t)ROWS * DIM];

// ---------------- helpers ----------------
__device__ __forceinline__ float exp2p(float y) {
    y = fmaxf(y, -126.0f);
    float z = y + 12582912.0f;
    int   n = __float_as_int(z) - 0x4B400000;
    float f = y - (z - 12582912.0f);
    float p = 1.33336e-3f;
    p = fmaf(p, f, 9.61813e-3f);
    p = fmaf(p, f, 5.55041e-2f);
    p = fmaf(p, f, 2.40226502e-1f);
    p = fmaf(p, f, 6.93147182e-1f);
    p = fmaf(p, f, 1.0f);
    return p * __int_as_float((n + 127) << 23);
}

__device__ __forceinline__ void mma_f16(float c[4], unsigned a0, unsigned a1, unsigned a2,
                                        unsigned a3, unsigned b0, unsigned b1) {
    asm volatile(
        "mma.sync.aligned.m16n8k16.row.col.f32.f16.f16.f32 "
        "{%0,%1,%2,%3}, {%4,%5,%6,%7}, {%8,%9}, {%0,%1,%2,%3};"
        : "+f"(c[0]), "+f"(c[1]), "+f"(c[2]), "+f"(c[3])
        : "r"(a0), "r"(a1), "r"(a2), "r"(a3), "r"(b0), "r"(b1));
}

__device__ __forceinline__ void ldsm4(unsigned r[4], unsigned addr) {
    asm volatile("ldmatrix.sync.aligned.m8n8.x4.shared.b16 {%0,%1,%2,%3}, [%4];"
                 : "=r"(r[0]), "=r"(r[1]), "=r"(r[2]), "=r"(r[3]) : "r"(addr));
}

__device__ __forceinline__ void ldsm4t(unsigned r[4], unsigned addr) {
    asm volatile("ldmatrix.sync.aligned.m8n8.x4.trans.shared.b16 {%0,%1,%2,%3}, [%4];"
                 : "=r"(r[0]), "=r"(r[1]), "=r"(r[2]), "=r"(r[3]) : "r"(addr));
}

__device__ __forceinline__ unsigned packh2(float lo, float hi) {
    __half2 h = __floats2half2_rn(lo, hi);
    return *(unsigned*)&h;
}

__device__ __forceinline__ void cpasync16(unsigned dst, const void* src) {
    asm volatile("cp.async.ca.shared.global [%0], [%1], 16;" :: "r"(dst), "l"(src));
}
// cp.async with zero-fill when invalid (src_size = 0 reads nothing)
__device__ __forceinline__ void cpasync16z(unsigned dst, const void* src, bool valid) {
    unsigned v = valid ? 16u : 0u;
    asm volatile("cp.async.ca.shared.global [%0], [%1], 16, %2;"
                 :: "r"(dst), "l"(src), "r"(v));
}
__device__ __forceinline__ void cpcommit() {
    asm volatile("cp.async.commit_group;");
}
template <int N>
__device__ __forceinline__ void cpwait() {
    asm volatile("cp.async.wait_group %0;" :: "n"(N));
}

// ---------------- weight fp32 -> fp16 ----------------
__global__ __launch_bounds__(256) void f2h_kernel(const float* __restrict__ s,
                                                  __half* __restrict__ d, int n4) {
    int i = blockIdx.x * 256 + threadIdx.x;
    if (i < n4) {
        float4 v = ((const float4*)s)[i];
        __half2 h0 = __floats2half2_rn(v.x, v.y);
        __half2 h1 = __floats2half2_rn(v.z, v.w);
        ((uint2*)d)[i] = make_uint2(*(unsigned*)&h0, *(unsigned*)&h1);
    }
}

// ---------------- RMSNorm (fp16 out) ----------------
__global__ __launch_bounds__(256) void rmsnorm_kernel(const float* __restrict__ seq,
                                                      const float* __restrict__ g,
                                                      __half* __restrict__ xnh) {
    int row = blockIdx.x;
    int tid = threadIdx.x;
    const float4* in = (const float4*)(seq + (size_t)row * DIM);
    float4 v = in[tid];
    float ss = v.x * v.x + v.y * v.y + v.z * v.z + v.w * v.w;
    #pragma unroll
    for (int o = 16; o; o >>= 1) ss += __shfl_xor_sync(0xFFFFFFFFu, ss, o);
    __shared__ float wsum[8];
    __shared__ float srms;
    if ((tid & 31) == 0) wsum[tid >> 5] = ss;
    __syncthreads();
    if (tid == 0) {
        float t = 0.f;
        #pragma unroll
        for (int i = 0; i < 8; i++) t += wsum[i];
        srms = rsqrtf(t * (1.0f / DIM) + RMS_EPS);
    }
    __syncthreads();
    float r = srms;
    float4 gv = ((const float4*)g)[tid];
    __half2 h0 = __floats2half2_rn(v.x * r * gv.x, v.y * r * gv.y);
    __half2 h1 = __floats2half2_rn(v.z * r * gv.z, v.w * r * gv.w);
    ((uint2*)(xnh + (size_t)row * DIM))[tid] = make_uint2(*(unsigned*)&h0, *(unsigned*)&h1);
}

// ---------------- FP16 GEMM: C[M,N] = A[M,K] * B[N,K]^T (templated output) --------
#define BM 128
#define BN 128
#define KC 64
#define HS 72
#define SSZ (BM * HS)
#define GEMM_SMEM (2 * 2 * SSZ * 2)

__device__ __forceinline__ void store2(float* p, float a, float b) {
    *(float2*)p = make_float2(a, b);
}
__device__ __forceinline__ void store2(__half* p, float a, float b) {
    *(unsigned*)p = packh2(a, b);
}

template <typename OutT>
__global__ __launch_bounds__(256) void hgemm(const __half* __restrict__ A,
                                             const __half* __restrict__ Bm,
                                             OutT* __restrict__ C,
                                             int M, int Nn, int K) {
    extern __shared__ __half sh[];
    unsigned smem_base = (unsigned)__cvta_generic_to_shared(sh);

    int tid = threadIdx.x;
    int bm = blockIdx.y * BM;
    int bn = blockIdx.x * BN;

    int wid  = tid >> 5;
    int lane = tid & 31;
    int warp_m = (wid & 3) * 32;
    int warp_n = (wid >> 2) * 64;
    int grp = lane >> 2;
    int qid = lane & 3;

    float c[2][8][4];
    #pragma unroll
    for (int i = 0; i < 2; i++)
        #pragma unroll
        for (int j = 0; j < 8; j++)
            #pragma unroll
            for (int u = 0; u < 4; u++) c[i][j][u] = 0.f;

    const int NT = K / KC;

    auto issue = [&](int kt, int s) {
        unsigned sb = smem_base + (unsigned)(s * 2 * SSZ * 2);
        int k0 = kt * KC;
        #pragma unroll
        for (int i = 0; i < 4; i++) {
            int chunk = tid + 256 * i;
            int row = chunk >> 3;
            int c8 = (chunk & 7) * 8;
            unsigned off = (unsigned)(row * HS + c8) * 2;
            cpasync16(sb + off, A + (size_t)(bm + row) * K + k0 + c8);
            cpasync16(sb + (unsigned)(SSZ * 2) + off, Bm + (size_t)(bn + row) * K + k0 + c8);
        }
        cpcommit();
    };

    int aRow = warp_m + (lane & 15);
    int aCol = (lane & 16) >> 1;
    int nOff = (lane & 7) | ((lane & 16) >> 1);
    int kOff = lane & 8;

    issue(0, 0);

    for (int kt = 0; kt < NT; kt++) {
        if (kt + 1 < NT) {
            issue(kt + 1, (kt + 1) & 1);
            cpwait<1>();
        } else {
            cpwait<0>();
        }
        __syncthreads();

        unsigned sb = smem_base + (unsigned)((kt & 1) * 2 * SSZ * 2);
        unsigned aAddr = sb + (unsigned)(aRow * HS + aCol) * 2;
        unsigned bAddr = sb + (unsigned)(SSZ * 2) + (unsigned)((warp_n + nOff) * HS + kOff) * 2;

        #pragma unroll
        for (int ks = 0; ks < 4; ks++) {
            unsigned a0[4], a1[4];
            ldsm4(a0, aAddr + ks * 32);
            ldsm4(a1, aAddr + (unsigned)(16 * HS * 2) + ks * 32);
            unsigned bf[4][4];
            #pragma unroll
            for (int nt = 0; nt < 4; nt++)
                ldsm4(bf[nt], bAddr + (unsigned)(nt * 16 * HS * 2) + ks * 32);
            #pragma unroll
            for (int nt = 0; nt < 4; nt++) {
                mma_f16(c[0][2 * nt    ], a0[0], a0[1], a0[2], a0[3], bf[nt][0], bf[nt][1]);
                mma_f16(c[0][2 * nt + 1], a0[0], a0[1], a0[2], a0[3], bf[nt][2], bf[nt][3]);
                mma_f16(c[1][2 * nt    ], a1[0], a1[1], a1[2], a1[3], bf[nt][0], bf[nt][1]);
                mma_f16(c[1][2 * nt + 1], a1[0], a1[1], a1[2], a1[3], bf[nt][2], bf[nt][3]);
            }
        }
        __syncthreads();
    }

    #pragma unroll
    for (int mf = 0; mf < 2; mf++) {
        int row0 = bm + warp_m + mf * 16 + grp;
        #pragma unroll
        for (int nf = 0; nf < 8; nf++) {
            int col = bn + warp_n + nf * 8 + qid * 2;
            store2(C + (size_t)row0 * Nn + col,       c[mf][nf][0], c[mf][nf][1]);
            store2(C + (size_t)(row0 + 8) * Nn + col, c[mf][nf][2], c[mf][nf][3]);
        }
    }
}

// ---------------- persistent-memory prepend (half) ----------------
__global__ __launch_bounds__(1024) void pm_fill(const float* __restrict__ pm,
                                                __half* __restrict__ k,
                                                __half* __restrict__ v) {
    int bwh = blockIdx.x;
    int h = bwh & 15;
    int t = threadIdx.x;
    int p = t >> 6;
    int d = t & 63;
    float kv_ = pm[((size_t)h * PMEM + p) * DH + d];
    float vv_ = pm[(size_t)HEADS * PMEM * DH + ((size_t)h * PMEM + p) * DH + d];
    k[((size_t)bwh * KV + p) * DH + d] = __float2half(kv_);
    v[((size_t)bwh * KV + p) * DH + d] = __float2half(vv_);
}

// ---------------- RoPE + reshape + segment scatter (half in/out, Q pre-scaled) -----
#define QSC (0.125f * 1.4426950408889634f)

__global__ __launch_bounds__(512) void rope_scatter(const __half* __restrict__ qkv,
                                                    __half* __restrict__ q,
                                                    __half* __restrict__ k,
                                                    __half* __restrict__ v) {
    int m = blockIdx.x;
    int b = m >> 12;
    int npos = m & 4095;
    int t = threadIdx.x;
    int h = t >> 5;
    int d = (t & 31) * 2;

    const __half* row = qkv + (size_t)m * 3 * DIM;
    float2 qv = __half22float2(*(const __half2*)(row + h * DH + d));
    float2 kv2 = __half22float2(*(const __half2*)(row + DIM + h * DH + d));
    unsigned vv = *(const unsigned*)(row + 2 * DIM + h * DH + d);

    float inv = 1.0f / powf(10000.0f, (float)d * (1.0f / 64.0f));
    float ang = (float)npos * inv;
    float sn, cs;
    sincosf(ang, &sn, &cs);
    float2 qr, kr;
    qr.x = qv.x * cs - qv.y * sn;  qr.y = qv.y * cs + qv.x * sn;
    kr.x = kv2.x * cs - kv2.y * sn; kr.y = kv2.y * cs + kv2.x * sn;

    int w = npos >> 9;
    int sidx = npos & 511;
    int bwh = (b * WSEG + w) * HEADS + h;
    *(unsigned*)(q + ((size_t)bwh * SEG + sidx) * DH + d) = packh2(qr.x * QSC, qr.y * QSC);
    *(unsigned*)(k + ((size_t)bwh * KV + PMEM + sidx) * DH + d) = packh2(kr.x, kr.y);
    *(unsigned*)(v + ((size_t)bwh * KV + PMEM + sidx) * DH + d) = vv;
}

// ---------------- fp16 flash attention, cp.async double-buffered K/V --------------
#define SH2 72                          // smem half stride
#define QBYTES (128 * SH2 * 2)          // 18432
#define KVBYTES (64 * SH2 * 2)          // 9216
#define ATT_SMEM (QBYTES + 4 * KVBYTES) // 55296

__global__ __launch_bounds__(256) void attn_tc(const __half* __restrict__ Q,
                                               const __half* __restrict__ K,
                                               const __half* __restrict__ V,
                                               __half* __restrict__ AO) {
    extern __shared__ __half ash[];
    unsigned sbase = (unsigned)__cvta_generic_to_shared(ash);

    const int tid  = threadIdx.x;
    const int wid  = tid >> 5;
    const int lane = tid & 31;
    const int grp  = lane >> 2;
    const int qid  = lane & 3;
    const int bwh  = blockIdx.y;
    const int q0   = blockIdx.x * 128;
    const int wq0  = q0 + wid * 16;

    const __half* Qb = Q + (size_t)bwh * SEG * DH;
    const __half* Kb = K + (size_t)bwh * KV * DH;
    const __half* Vb = V + (size_t)bwh * KV * DH;

    const int r  = tid >> 2;       // staging row 0..63
    const int c4 = tid & 3;        // 16-half chunk

    int jmax = q0 + 128 + PMEM;
    if (jmax > KV) jmax = KV;
    int ntiles = (jmax + 63) >> 6;

    // issue cp.async staging of KV tile t into stage s
    auto issueKV = [&](int t, int s) {
        unsigned kb = sbase + (unsigned)(QBYTES + s * 2 * KVBYTES);
        unsigned vb = kb + KVBYTES;
        int jj = t * 64 + r;
        bool valid = jj < KV;
        int jjc = valid ? jj : (KV - 1);
        const __half* kg = Kb + (size_t)jjc * DH + c4 * 16;
        const __half* vg = Vb + (size_t)jjc * DH + c4 * 16;
        unsigned off = (unsigned)(r * SH2 + c4 * 16) * 2;
        cpasync16z(kb + off,      kg,     valid);
        cpasync16z(kb + off + 16, kg + 8, valid);
        cpasync16z(vb + off,      vg,     valid);
        cpasync16z(vb + off + 16, vg + 8, valid);
        cpcommit();
    };

    issueKV(0, 0);

    // ---- stage Q tile, extract A-fragments ----
    {
        __half* sQp = ash;
        #pragma unroll
        for (int i = 0; i < 4; i++) {
            int chunk = tid + 256 * i;
            int row = chunk >> 3;
            int off = (chunk & 7) * 8;
            *(uint4*)(sQp + row * SH2 + off) = *(const uint4*)(Qb + (size_t)(q0 + row) * DH + off);
        }
    }
    __syncthreads();

    unsigned aq[4][4];
    {
        int aRow = wid * 16 + (lane & 15);
        int aCol = (lane & 16) >> 1;
        #pragma unroll
        for (int kc = 0; kc < 4; kc++)
            ldsm4(aq[kc], sbase + (unsigned)(aRow * SH2 + kc * 16 + aCol) * 2);
    }

    float o[8][4];
    #pragma unroll
    for (int nf = 0; nf < 8; nf++)
        #pragma unroll
        for (int u = 0; u < 4; u++) o[nf][u] = 0.f;
    float m0 = -1e30f, m1 = -1e30f, l0 = 0.f, l1 = 0.f;

    const int fRow = lane & 15;
    const int fCol = (lane & 16) >> 1;
    const int nRow = (lane & 7) | ((lane & 16) >> 1);
    const int kOff = lane & 8;

    for (int t = 0; t < ntiles; t++) {
        int jj0 = t << 6;
        if (t + 1 < ntiles) {
            issueKV(t + 1, (t + 1) & 1);
            cpwait<1>();
        } else {
            cpwait<0>();
        }
        __syncthreads();

        unsigned sKb = sbase + (unsigned)(QBYTES + (t & 1) * 2 * KVBYTES);
        unsigned sVb = sKb + KVBYTES;

        if (jj0 <= wq0 + 15 + PMEM) {
            float c[8][4];
            #pragma unroll
            for (int nf = 0; nf < 8; nf++)
                #pragma unroll
                for (int u = 0; u < 4; u++) c[nf][u] = 0.f;

            #pragma unroll
            for (int kc = 0; kc < 4; kc++) {
                #pragma unroll
                for (int ng = 0; ng < 4; ng++) {
                    unsigned b[4];
                    ldsm4(b, sKb + (unsigned)((ng * 16 + nRow) * SH2 + kc * 16 + kOff) * 2);
                    mma_f16(c[2 * ng    ], aq[kc][0], aq[kc][1], aq[kc][2], aq[kc][3], b[0], b[1]);
                    mma_f16(c[2 * ng + 1], aq[kc][0], aq[kc][1], aq[kc][2], aq[kc][3], b[2], b[3]);
                }
            }

            if (jj0 + 63 > wq0 + PMEM) {
                int r0 = wq0 + grp, r1 = r0 + 8;
                #pragma unroll
                for (int nf = 0; nf < 8; nf++) {
                    int j0 = jj0 + nf * 8 + 2 * qid;
                    if (j0     - PMEM > r0) c[nf][0] = -1e30f;
                    if (j0 + 1 - PMEM > r0) c[nf][1] = -1e30f;
                    if (j0     - PMEM > r1) c[nf][2] = -1e30f;
                    if (j0 + 1 - PMEM > r1) c[nf][3] = -1e30f;
                }
            }

            float mt0 = -1e30f, mt1 = -1e30f;
            #pragma unroll
            for (int nf = 0; nf < 8; nf++) {
                mt0 = fmaxf(mt0, fmaxf(c[nf][0], c[nf][1]));
                mt1 = fmaxf(mt1, fmaxf(c[nf][2], c[nf][3]));
            }
            mt0 = fmaxf(mt0, __shfl_xor_sync(0xFFFFFFFFu, mt0, 1));
            mt0 = fmaxf(mt0, __shfl_xor_sync(0xFFFFFFFFu, mt0, 2));
            mt1 = fmaxf(mt1, __shfl_xor_sync(0xFFFFFFFFu, mt1, 1));
            mt1 = fmaxf(mt1, __shfl_xor_sync(0xFFFFFFFFu, mt1, 2));

            float nm0 = fmaxf(m0, mt0), nm1 = fmaxf(m1, mt1);
            float f0 = exp2p(m0 - nm0), f1 = exp2p(m1 - nm1);
            m0 = nm0; m1 = nm1;
            l0 *= f0; l1 *= f1;
            #pragma unroll
            for (int nf = 0; nf < 8; nf++) {
                o[nf][0] *= f0; o[nf][1] *= f0;
                o[nf][2] *= f1; o[nf][3] *= f1;
            }

            float s0 = 0.f, s1 = 0.f;
            #pragma unroll
            for (int nf = 0; nf < 8; nf++) {
                float p00 = exp2p(c[nf][0] - m0);
                float p01 = exp2p(c[nf][1] - m0);
                float p10 = exp2p(c[nf][2] - m1);
                float p11 = exp2p(c[nf][3] - m1);
                c[nf][0] = p00; c[nf][1] = p01; c[nf][2] = p10; c[nf][3] = p11;
                s0 += p00 + p01; s1 += p10 + p11;
            }
            s0 += __shfl_xor_sync(0xFFFFFFFFu, s0, 1);
            s0 += __shfl_xor_sync(0xFFFFFFFFu, s0, 2);
            s1 += __shfl_xor_sync(0xFFFFFFFFu, s1, 1);
            s1 += __shfl_xor_sync(0xFFFFFFFFu, s1, 2);
            l0 += s0; l1 += s1;

            unsigned ph[4][4];
            #pragma unroll
            for (int kc = 0; kc < 4; kc++) {
                ph[kc][0] = packh2(c[2 * kc    ][0], c[2 * kc    ][1]);
                ph[kc][1] = packh2(c[2 * kc    ][2], c[2 * kc    ][3]);
                ph[kc][2] = packh2(c[2 * kc + 1][0], c[2 * kc + 1][1]);
                ph[kc][3] = packh2(c[2 * kc + 1][2], c[2 * kc + 1][3]);
            }

            #pragma unroll
            for (int kc = 0; kc < 4; kc++) {
                #pragma unroll
                for (int dg = 0; dg < 4; dg++) {
                    unsigned b[4];
                    ldsm4t(b, sVb + (unsigned)((kc * 16 + fRow) * SH2 + dg * 16 + fCol) * 2);
                    mma_f16(o[2 * dg    ], ph[kc][0], ph[kc][1], ph[kc][2], ph[kc][3], b[0], b[1]);
                    mma_f16(o[2 * dg + 1], ph[kc][0], ph[kc][1], ph[kc][2], ph[kc][3], b[2], b[3]);
                }
            }
        }
        __syncthreads();
    }

    float inv0 = 1.0f / l0, inv1 = 1.0f / l1;
    int bw = bwh >> 4, h = bwh & 15;
    int r0 = wq0 + grp, r1 = r0 + 8;
    __half* out0 = AO + (size_t)(bw * SEG + r0) * DIM + h * DH;
    __half* out1 = AO + (size_t)(bw * SEG + r1) * DIM + h * DH;
    #pragma unroll
    for (int nf = 0; nf < 8; nf++) {
        int col = nf * 8 + 2 * qid;
        *(unsigned*)(out0 + col) = packh2(o[nf][0] * inv0, o[nf][1] * inv0);
        *(unsigned*)(out1 + col) = packh2(o[nf][2] * inv1, o[nf][3] * inv1);
    }
}

// ---------------- launch ----------------
extern "C" void kernel_launch(void* const* d_in, const int* in_sizes, int n_in,
                              void* d_out, int out_size) {
    const float* seq   = (const float*)d_in[0];
    const float* g     = (const float*)d_in[1];
    const float* w_qkv = (const float*)d_in[2];
    const float* w_out = (const float*)d_in[3];
    const float* pm    = (const float*)d_in[4];
    float* out = (float*)d_out;

    __half *xnh, *whq, *who, *aoh, *q, *k, *v, *qkvh;
    cudaGetSymbolAddress((void**)&xnh, g_xnh);
    cudaGetSymbolAddress((void**)&whq, g_whq);
    cudaGetSymbolAddress((void**)&who, g_who);
    cudaGetSymbolAddress((void**)&qkvh, g_qkv);
    cudaGetSymbolAddress((void**)&q,   g_q);
    cudaGetSymbolAddress((void**)&k,   g_k);
    cudaGetSymbolAddress((void**)&v,   g_v);
    cudaGetSymbolAddress((void**)&aoh, g_aoh);

    static int smem_set = 0;
    if (!smem_set) {
        cudaFuncSetAttribute(hgemm<__half>, cudaFuncAttributeMaxDynamicSharedMemorySize, GEMM_SMEM);
        cudaFuncSetAttribute(hgemm<float>,  cudaFuncAttributeMaxDynamicSharedMemorySize, GEMM_SMEM);
        cudaFuncSetAttribute(attn_tc, cudaFuncAttributeMaxDynamicSharedMemorySize, ATT_SMEM);
        smem_set = 1;
    }

    f2h_kernel<<<(3 * DIM * DIM / 4 + 255) / 256, 256>>>(w_qkv, whq, 3 * DIM * DIM / 4);
    f2h_kernel<<<(DIM * DIM / 4 + 255) / 256, 256>>>(w_out, who, DIM * DIM / 4);
    rmsnorm_kernel<<<ROWS, 256>>>(seq, g, xnh);
    hgemm<__half><<<dim3(3 * DIM / BN, ROWS / BM), 256, GEMM_SMEM>>>(xnh, whq, qkvh, ROWS, 3 * DIM, DIM);
    pm_fill<<<BW * HEADS, 1024>>>(pm, k, v);
    rope_scatter<<<ROWS, 512>>>(qkvh, q, k, v);
    attn_tc<<<dim3(4, BW * HEADS), 256, ATT_SMEM>>>(q, k, v, aoh);
    hgemm<float><<<dim3(DIM / BN, ROWS / BM), 256, GEMM_SMEM>>>(aoh, who, out, ROWS, DIM, DIM);
}

// round 12
// speedup vs baseline: 6.6450x; 1.0296x over previous
#include <cuda_runtime.h>
#include <cuda_fp16.h>
#include <cstdint>
#include <math.h>

#define DIM    1024
#define HEADS  16
#define DH     64
#define SEG    512
#define PMEM   16
#define BATCH  2
#define NSEQ   4096
#define WSEG   (NSEQ / SEG)       // 8
#define BW     (BATCH * WSEG)     // 16
#define ROWS   (BATCH * NSEQ)     // 8192
#define KV     (SEG + PMEM)       // 528
#define RMS_EPS 1.1920929e-07f
#define QSC (0.125f * 1.4426950408889634f)

// ---------------- scratch (no cudaMalloc allowed) ----------------
__device__ __half g_xnh[(size_t)ROWS * DIM];
__device__ __half g_whq[(size_t)3 * DIM * DIM];
__device__ __half g_who[(size_t)DIM * DIM];
__device__ __half g_q  [(size_t)BW * HEADS * SEG * DH];
__device__ __half g_k  [(size_t)BW * HEADS * KV  * DH];
__device__ __half g_v  [(size_t)BW * HEADS * KV  * DH];
__device__ __half g_aoh[(size_t)ROWS * DIM];

// ---------------- helpers ----------------
__device__ __forceinline__ float exp2p(float y) {
    y = fmaxf(y, -126.0f);
    float z = y + 12582912.0f;
    int   n = __float_as_int(z) - 0x4B400000;
    float f = y - (z - 12582912.0f);
    float p = 1.33336e-3f;
    p = fmaf(p, f, 9.61813e-3f);
    p = fmaf(p, f, 5.55041e-2f);
    p = fmaf(p, f, 2.40226502e-1f);
    p = fmaf(p, f, 6.93147182e-1f);
    p = fmaf(p, f, 1.0f);
    return p * __int_as_float((n + 127) << 23);
}

__device__ __forceinline__ void mma_f16(float c[4], unsigned a0, unsigned a1, unsigned a2,
                                        unsigned a3, unsigned b0, unsigned b1) {
    asm volatile(
        "mma.sync.aligned.m16n8k16.row.col.f32.f16.f16.f32 "
        "{%0,%1,%2,%3}, {%4,%5,%6,%7}, {%8,%9}, {%0,%1,%2,%3};"
        : "+f"(c[0]), "+f"(c[1]), "+f"(c[2]), "+f"(c[3])
        : "r"(a0), "r"(a1), "r"(a2), "r"(a3), "r"(b0), "r"(b1));
}

__device__ __forceinline__ void ldsm4(unsigned r[4], unsigned addr) {
    asm volatile("ldmatrix.sync.aligned.m8n8.x4.shared.b16 {%0,%1,%2,%3}, [%4];"
                 : "=r"(r[0]), "=r"(r[1]), "=r"(r[2]), "=r"(r[3]) : "r"(addr));
}

__device__ __forceinline__ void ldsm4t(unsigned r[4], unsigned addr) {
    asm volatile("ldmatrix.sync.aligned.m8n8.x4.trans.shared.b16 {%0,%1,%2,%3}, [%4];"
                 : "=r"(r[0]), "=r"(r[1]), "=r"(r[2]), "=r"(r[3]) : "r"(addr));
}

__device__ __forceinline__ unsigned packh2(float lo, float hi) {
    __half2 h = __floats2half2_rn(lo, hi);
    return *(unsigned*)&h;
}

__device__ __forceinline__ void cpasync16(unsigned dst, const void* src) {
    asm volatile("cp.async.ca.shared.global [%0], [%1], 16;" :: "r"(dst), "l"(src));
}
__device__ __forceinline__ void cpasync16z(unsigned dst, const void* src, bool valid) {
    unsigned v = valid ? 16u : 0u;
    asm volatile("cp.async.ca.shared.global [%0], [%1], 16, %2;"
                 :: "r"(dst), "l"(src), "r"(v));
}
__device__ __forceinline__ void cpcommit() {
    asm volatile("cp.async.commit_group;");
}
template <int N>
__device__ __forceinline__ void cpwait() {
    asm volatile("cp.async.wait_group %0;" :: "n"(N));
}

// ---------------- weight fp32 -> fp16 ----------------
__global__ __launch_bounds__(256) void f2h_kernel(const float* __restrict__ s,
                                                  __half* __restrict__ d, int n4) {
    int i = blockIdx.x * 256 + threadIdx.x;
    if (i < n4) {
        float4 v = ((const float4*)s)[i];
        __half2 h0 = __floats2half2_rn(v.x, v.y);
        __half2 h1 = __floats2half2_rn(v.z, v.w);
        ((uint2*)d)[i] = make_uint2(*(unsigned*)&h0, *(unsigned*)&h1);
    }
}

// ---------------- RMSNorm (fp16 out) ----------------
__global__ __launch_bounds__(256) void rmsnorm_kernel(const float* __restrict__ seq,
                                                      const float* __restrict__ g,
                                                      __half* __restrict__ xnh) {
    int row = blockIdx.x;
    int tid = threadIdx.x;
    const float4* in = (const float4*)(seq + (size_t)row * DIM);
    float4 v = in[tid];
    float ss = v.x * v.x + v.y * v.y + v.z * v.z + v.w * v.w;
    #pragma unroll
    for (int o = 16; o; o >>= 1) ss += __shfl_xor_sync(0xFFFFFFFFu, ss, o);
    __shared__ float wsum[8];
    __shared__ float srms;
    if ((tid & 31) == 0) wsum[tid >> 5] = ss;
    __syncthreads();
    if (tid == 0) {
        float t = 0.f;
        #pragma unroll
        for (int i = 0; i < 8; i++) t += wsum[i];
        srms = rsqrtf(t * (1.0f / DIM) + RMS_EPS);
    }
    __syncthreads();
    float r = srms;
    float4 gv = ((const float4*)g)[tid];
    __half2 h0 = __floats2half2_rn(v.x * r * gv.x, v.y * r * gv.y);
    __half2 h1 = __floats2half2_rn(v.z * r * gv.z, v.w * r * gv.w);
    ((uint2*)(xnh + (size_t)row * DIM))[tid] = make_uint2(*(unsigned*)&h0, *(unsigned*)&h1);
}

// ---------------- FP16 GEMM: C = A * B^T, single-sync 2-stage pipeline --------------
// QKV=true: fused RoPE + segment scatter epilogue into q/k/v (half).
// QKV=false: plain fp32 output.
#define BM 128
#define BN 128
#define KC 64
#define HS 72
#define SSZ (BM * HS)
#define GEMM_SMEM (2 * 2 * SSZ * 2)

template <bool QKV>
__global__ __launch_bounds__(256) void hgemm(const __half* __restrict__ A,
                                             const __half* __restrict__ Bm,
                                             float* __restrict__ C,
                                             __half* __restrict__ qo,
                                             __half* __restrict__ ko,
                                             __half* __restrict__ vo,
                                             int Nn, int K) {
    extern __shared__ __half sh[];
    unsigned smem_base = (unsigned)__cvta_generic_to_shared(sh);

    int tid = threadIdx.x;
    int bm = blockIdx.y * BM;
    int bn = blockIdx.x * BN;

    int wid  = tid >> 5;
    int lane = tid & 31;
    int warp_m = (wid & 3) * 32;
    int warp_n = (wid >> 2) * 64;
    int grp = lane >> 2;
    int qid = lane & 3;

    float c[2][8][4];
    #pragma unroll
    for (int i = 0; i < 2; i++)
        #pragma unroll
        for (int j = 0; j < 8; j++)
            #pragma unroll
            for (int u = 0; u < 4; u++) c[i][j][u] = 0.f;

    const int NT = K / KC;

    auto issue = [&](int kt, int s) {
        unsigned sb = smem_base + (unsigned)(s * 2 * SSZ * 2);
        int k0 = kt * KC;
        #pragma unroll
        for (int i = 0; i < 4; i++) {
            int chunk = tid + 256 * i;
            int row = chunk >> 3;
            int c8 = (chunk & 7) * 8;
            unsigned off = (unsigned)(row * HS + c8) * 2;
            cpasync16(sb + off, A + (size_t)(bm + row) * K + k0 + c8);
            cpasync16(sb + (unsigned)(SSZ * 2) + off, Bm + (size_t)(bn + row) * K + k0 + c8);
        }
        cpcommit();
    };

    int aRow = warp_m + (lane & 15);
    int aCol = (lane & 16) >> 1;
    int nOff = (lane & 7) | ((lane & 16) >> 1);
    int kOff = lane & 8;

    issue(0, 0);

    for (int kt = 0; kt < NT; kt++) {
        cpwait<0>();
        __syncthreads();
        if (kt + 1 < NT) issue(kt + 1, (kt + 1) & 1);

        unsigned sb = smem_base + (unsigned)((kt & 1) * 2 * SSZ * 2);
        unsigned aAddr = sb + (unsigned)(aRow * HS + aCol) * 2;
        unsigned bAddr = sb + (unsigned)(SSZ * 2) + (unsigned)((warp_n + nOff) * HS + kOff) * 2;

        #pragma unroll
        for (int ks = 0; ks < 4; ks++) {
            unsigned a0[4], a1[4];
            ldsm4(a0, aAddr + ks * 32);
            ldsm4(a1, aAddr + (unsigned)(16 * HS * 2) + ks * 32);
            unsigned bf[4][4];
            #pragma unroll
            for (int nt = 0; nt < 4; nt++)
                ldsm4(bf[nt], bAddr + (unsigned)(nt * 16 * HS * 2) + ks * 32);
            #pragma unroll
            for (int nt = 0; nt < 4; nt++) {
                mma_f16(c[0][2 * nt    ], a0[0], a0[1], a0[2], a0[3], bf[nt][0], bf[nt][1]);
                mma_f16(c[0][2 * nt + 1], a0[0], a0[1], a0[2], a0[3], bf[nt][2], bf[nt][3]);
                mma_f16(c[1][2 * nt    ], a1[0], a1[1], a1[2], a1[3], bf[nt][0], bf[nt][1]);
                mma_f16(c[1][2 * nt + 1], a1[0], a1[1], a1[2], a1[3], bf[nt][2], bf[nt][3]);
            }
        }
    }

    if (!QKV) {
        #pragma unroll
        for (int mf = 0; mf < 2; mf++) {
            int row0 = bm + warp_m + mf * 16 + grp;
            #pragma unroll
            for (int nf = 0; nf < 8; nf++) {
                int col = bn + warp_n + nf * 8 + qid * 2;
                *(float2*)(C + (size_t)row0 * Nn + col)       = make_float2(c[mf][nf][0], c[mf][nf][1]);
                *(float2*)(C + (size_t)(row0 + 8) * Nn + col) = make_float2(c[mf][nf][2], c[mf][nf][3]);
            }
        }
    } else {
        // fused RoPE + segment scatter. `which` (q/k/v) is uniform per CTA.
        int which = (bn + warp_n) >> 10;
        float invf[8];
        if (which != 2) {
            #pragma unroll
            for (int nf = 0; nf < 8; nf++) {
                int d = (bn + warp_n + nf * 8 + qid * 2) & 63;
                invf[nf] = 1.0f / powf(10000.0f, (float)d * (1.0f / 64.0f));
            }
        }
        #pragma unroll
        for (int mf = 0; mf < 2; mf++) {
            #pragma unroll
            for (int sub = 0; sub < 2; sub++) {
                int m = bm + warp_m + mf * 16 + grp + sub * 8;
                int b = m >> 12;
                int npos = m & 4095;
                int w = npos >> 9;
                int sidx = npos & 511;
                int bwx = (b * WSEG + w) * HEADS;
                #pragma unroll
                for (int nf = 0; nf < 8; nf++) {
                    int col = bn + warp_n + nf * 8 + qid * 2;
                    int h = (col >> 6) & 15;
                    int d = col & 63;
                    float x = c[mf][nf][2 * sub], y = c[mf][nf][2 * sub + 1];
                    int bwh = bwx + h;
                    if (which == 2) {
                        *(unsigned*)(vo + ((size_t)bwh * KV + PMEM + sidx) * DH + d) = packh2(x, y);
                    } else {
                        float ang = (float)npos * invf[nf];
                        float sn, cs;
                        sincosf(ang, &sn, &cs);
                        float rx = x * cs - y * sn;
                        float ry = y * cs + x * sn;
                        if (which == 0)
                            *(unsigned*)(qo + ((size_t)bwh * SEG + sidx) * DH + d) = packh2(rx * QSC, ry * QSC);
                        else
                            *(unsigned*)(ko + ((size_t)bwh * KV + PMEM + sidx) * DH + d) = packh2(rx, ry);
                    }
                }
            }
        }
    }
}

// ---------------- persistent-memory prepend (half) ----------------
__global__ __launch_bounds__(1024) void pm_fill(const float* __restrict__ pm,
                                                __half* __restrict__ k,
                                                __half* __restrict__ v) {
    int bwh = blockIdx.x;
    int h = bwh & 15;
    int t = threadIdx.x;
    int p = t >> 6;
    int d = t & 63;
    float kv_ = pm[((size_t)h * PMEM + p) * DH + d];
    float vv_ = pm[(size_t)HEADS * PMEM * DH + ((size_t)h * PMEM + p) * DH + d];
    k[((size_t)bwh * KV + p) * DH + d] = __float2half(kv_);
    v[((size_t)bwh * KV + p) * DH + d] = __float2half(vv_);
}

// ---------------- fp16 flash attention, single-sync 2-stage cp.async --------------
#define SH2 72
#define QBYTES (128 * SH2 * 2)
#define KVBYTES (64 * SH2 * 2)
#define ATT_SMEM (QBYTES + 4 * KVBYTES)

__global__ __launch_bounds__(256) void attn_tc(const __half* __restrict__ Q,
                                               const __half* __restrict__ K,
                                               const __half* __restrict__ V,
                                               __half* __restrict__ AO) {
    extern __shared__ __half ash[];
    unsigned sbase = (unsigned)__cvta_generic_to_shared(ash);

    const int tid  = threadIdx.x;
    const int wid  = tid >> 5;
    const int lane = tid & 31;
    const int grp  = lane >> 2;
    const int qid  = lane & 3;
    const int bwh  = blockIdx.y;
    const int q0   = blockIdx.x * 128;
    const int wq0  = q0 + wid * 16;

    const __half* Qb = Q + (size_t)bwh * SEG * DH;
    const __half* Kb = K + (size_t)bwh * KV * DH;
    const __half* Vb = V + (size_t)bwh * KV * DH;

    const int r  = tid >> 2;
    const int c4 = tid & 3;

    int jmax = q0 + 128 + PMEM;
    if (jmax > KV) jmax = KV;
    int ntiles = (jmax + 63) >> 6;

    auto issueKV = [&](int t, int s) {
        unsigned kb = sbase + (unsigned)(QBYTES + s * 2 * KVBYTES);
        unsigned vb = kb + KVBYTES;
        int jj = t * 64 + r;
        bool valid = jj < KV;
        int jjc = valid ? jj : (KV - 1);
        const __half* kg = Kb + (size_t)jjc * DH + c4 * 16;
        const __half* vg = Vb + (size_t)jjc * DH + c4 * 16;
        unsigned off = (unsigned)(r * SH2 + c4 * 16) * 2;
        cpasync16z(kb + off,      kg,     valid);
        cpasync16z(kb + off + 16, kg + 8, valid);
        cpasync16z(vb + off,      vg,     valid);
        cpasync16z(vb + off + 16, vg + 8, valid);
        cpcommit();
    };

    issueKV(0, 0);

    {
        __half* sQp = ash;
        #pragma unroll
        for (int i = 0; i < 4; i++) {
            int chunk = tid + 256 * i;
            int row = chunk >> 3;
            int off = (chunk & 7) * 8;
            *(uint4*)(sQp + row * SH2 + off) = *(const uint4*)(Qb + (size_t)(q0 + row) * DH + off);
        }
    }
    __syncthreads();

    unsigned aq[4][4];
    {
        int aRow = wid * 16 + (lane & 15);
        int aCol = (lane & 16) >> 1;
        #pragma unroll
        for (int kc = 0; kc < 4; kc++)
            ldsm4(aq[kc], sbase + (unsigned)(aRow * SH2 + kc * 16 + aCol) * 2);
    }

    float o[8][4];
    #pragma unroll
    for (int nf = 0; nf < 8; nf++)
        #pragma unroll
        for (int u = 0; u < 4; u++) o[nf][u] = 0.f;
    float m0 = -1e30f, m1 = -1e30f, l0 = 0.f, l1 = 0.f;

    const int fRow = lane & 15;
    const int fCol = (lane & 16) >> 1;
    const int nRow = (lane & 7) | ((lane & 16) >> 1);
    const int kOff = lane & 8;

    for (int t = 0; t < ntiles; t++) {
        int jj0 = t << 6;
        cpwait<0>();
        __syncthreads();
        if (t + 1 < ntiles) issueKV(t + 1, (t + 1) & 1);

        unsigned sKb = sbase + (unsigned)(QBYTES + (t & 1) * 2 * KVBYTES);
        unsigned sVb = sKb + KVBYTES;

        if (jj0 <= wq0 + 15 + PMEM) {
            float c[8][4];
            #pragma unroll
            for (int nf = 0; nf < 8; nf++)
                #pragma unroll
                for (int u = 0; u < 4; u++) c[nf][u] = 0.f;

            #pragma unroll
            for (int kc = 0; kc < 4; kc++) {
                #pragma unroll
                for (int ng = 0; ng < 4; ng++) {
                    unsigned b[4];
                    ldsm4(b, sKb + (unsigned)((ng * 16 + nRow) * SH2 + kc * 16 + kOff) * 2);
                    mma_f16(c[2 * ng    ], aq[kc][0], aq[kc][1], aq[kc][2], aq[kc][3], b[0], b[1]);
                    mma_f16(c[2 * ng + 1], aq[kc][0], aq[kc][1], aq[kc][2], aq[kc][3], b[2], b[3]);
                }
            }

            if (jj0 + 63 > wq0 + PMEM) {
                int r0 = wq0 + grp, r1 = r0 + 8;
                #pragma unroll
                for (int nf = 0; nf < 8; nf++) {
                    int j0 = jj0 + nf * 8 + 2 * qid;
                    if (j0     - PMEM > r0) c[nf][0] = -1e30f;
                    if (j0 + 1 - PMEM > r0) c[nf][1] = -1e30f;
                    if (j0     - PMEM > r1) c[nf][2] = -1e30f;
                    if (j0 + 1 - PMEM > r1) c[nf][3] = -1e30f;
                }
            }

            float mt0 = -1e30f, mt1 = -1e30f;
            #pragma unroll
            for (int nf = 0; nf < 8; nf++) {
                mt0 = fmaxf(mt0, fmaxf(c[nf][0], c[nf][1]));
                mt1 = fmaxf(mt1, fmaxf(c[nf][2], c[nf][3]));
            }
            mt0 = fmaxf(mt0, __shfl_xor_sync(0xFFFFFFFFu, mt0, 1));
            mt0 = fmaxf(mt0, __shfl_xor_sync(0xFFFFFFFFu, mt0, 2));
            mt1 = fmaxf(mt1, __shfl_xor_sync(0xFFFFFFFFu, mt1, 1));
            mt1 = fmaxf(mt1, __shfl_xor_sync(0xFFFFFFFFu, mt1, 2));

            float nm0 = fmaxf(m0, mt0), nm1 = fmaxf(m1, mt1);
            float f0 = exp2p(m0 - nm0), f1 = exp2p(m1 - nm1);
            m0 = nm0; m1 = nm1;
            l0 *= f0; l1 *= f1;
            #pragma unroll
            for (int nf = 0; nf < 8; nf++) {
                o[nf][0] *= f0; o[nf][1] *= f0;
                o[nf][2] *= f1; o[nf][3] *= f1;
            }

            float s0 = 0.f, s1 = 0.f;
            #pragma unroll
            for (int nf = 0; nf < 8; nf++) {
                float p00 = exp2p(c[nf][0] - m0);
                float p01 = exp2p(c[nf][1] - m0);
                float p10 = exp2p(c[nf][2] - m1);
                float p11 = exp2p(c[nf][3] - m1);
                c[nf][0] = p00; c[nf][1] = p01; c[nf][2] = p10; c[nf][3] = p11;
                s0 += p00 + p01; s1 += p10 + p11;
            }
            s0 += __shfl_xor_sync(0xFFFFFFFFu, s0, 1);
            s0 += __shfl_xor_sync(0xFFFFFFFFu, s0, 2);
            s1 += __shfl_xor_sync(0xFFFFFFFFu, s1, 1);
            s1 += __shfl_xor_sync(0xFFFFFFFFu, s1, 2);
            l0 += s0; l1 += s1;

            unsigned ph[4][4];
            #pragma unroll
            for (int kc = 0; kc < 4; kc++) {
                ph[kc][0] = packh2(c[2 * kc    ][0], c[2 * kc    ][1]);
                ph[kc][1] = packh2(c[2 * kc    ][2], c[2 * kc    ][3]);
                ph[kc][2] = packh2(c[2 * kc + 1][0], c[2 * kc + 1][1]);
                ph[kc][3] = packh2(c[2 * kc + 1][2], c[2 * kc + 1][3]);
            }

            #pragma unroll
            for (int kc = 0; kc < 4; kc++) {
                #pragma unroll
                for (int dg = 0; dg < 4; dg++) {
                    unsigned b[4];
                    ldsm4t(b, sVb + (unsigned)((kc * 16 + fRow) * SH2 + dg * 16 + fCol) * 2);
                    mma_f16(o[2 * dg    ], ph[kc][0], ph[kc][1], ph[kc][2], ph[kc][3], b[0], b[1]);
                    mma_f16(o[2 * dg + 1], ph[kc][0], ph[kc][1], ph[kc][2], ph[kc][3], b[2], b[3]);
                }
            }
        }
    }

    float inv0 = 1.0f / l0, inv1 = 1.0f / l1;
    int bw = bwh >> 4, h = bwh & 15;
    int r0 = wq0 + grp, r1 = r0 + 8;
    __half* out0 = AO + (size_t)(bw * SEG + r0) * DIM + h * DH;
    __half* out1 = AO + (size_t)(bw * SEG + r1) * DIM + h * DH;
    #pragma unroll
    for (int nf = 0; nf < 8; nf++) {
        int col = nf * 8 + 2 * qid;
        *(unsigned*)(out0 + col) = packh2(o[nf][0] * inv0, o[nf][1] * inv0);
        *(unsigned*)(out1 + col) = packh2(o[nf][2] * inv1, o[nf][3] * inv1);
    }
}

// ---------------- launch ----------------
extern "C" void kernel_launch(void* const* d_in, const int* in_sizes, int n_in,
                              void* d_out, int out_size) {
    const float* seq   = (const float*)d_in[0];
    const float* g     = (const float*)d_in[1];
    const float* w_qkv = (const float*)d_in[2];
    const float* w_out = (const float*)d_in[3];
    const float* pm    = (const float*)d_in[4];
    float* out = (float*)d_out;

    __half *xnh, *whq, *who, *aoh, *q, *k, *v;
    cudaGetSymbolAddress((void**)&xnh, g_xnh);
    cudaGetSymbolAddress((void**)&whq, g_whq);
    cudaGetSymbolAddress((void**)&who, g_who);
    cudaGetSymbolAddress((void**)&q,   g_q);
    cudaGetSymbolAddress((void**)&k,   g_k);
    cudaGetSymbolAddress((void**)&v,   g_v);
    cudaGetSymbolAddress((void**)&aoh, g_aoh);

    static int smem_set = 0;
    if (!smem_set) {
        cudaFuncSetAttribute(hgemm<true>,  cudaFuncAttributeMaxDynamicSharedMemorySize, GEMM_SMEM);
        cudaFuncSetAttribute(hgemm<false>, cudaFuncAttributeMaxDynamicSharedMemorySize, GEMM_SMEM);
        cudaFuncSetAttribute(attn_tc, cudaFuncAttributeMaxDynamicSharedMemorySize, ATT_SMEM);
        smem_set = 1;
    }

    f2h_kernel<<<(3 * DIM * DIM / 4 + 255) / 256, 256>>>(w_qkv, whq, 3 * DIM * DIM / 4);
    f2h_kernel<<<(DIM * DIM / 4 + 255) / 256, 256>>>(w_out, who, DIM * DIM / 4);
    rmsnorm_kernel<<<ROWS, 256>>>(seq, g, xnh);
    pm_fill<<<BW * HEADS, 1024>>>(pm, k, v);
    hgemm<true><<<dim3(3 * DIM / BN, ROWS / BM), 256, GEMM_SMEM>>>(xnh, whq, nullptr, q, k, v, 3 * DIM, DIM);
    attn_tc<<<dim3(4, BW * HEADS), 256, ATT_SMEM>>>(q, k, v, aoh);
    hgemm<false><<<dim3(DIM / BN, ROWS / BM), 256, GEMM_SMEM>>>(aoh, who, out, nullptr, nullptr, nullptr, DIM, DIM);
}